// round 8
// baseline (speedup 1.0000x reference)
#include <cuda_runtime.h>
#include <cuda_fp16.h>
#include <math.h>

// ---------------- problem dims ----------------
#define B_  4
#define T_  2048
#define C_  1024
#define H_  8
#define DH_ 128
#define DFF_ 4096
#define ROWS_ (B_*T_)          // 8192

typedef unsigned int u32;

// ---------------- scratch (device globals; no allocs allowed) ----------------
__device__ __align__(16) __half g_hH[ROWS_*C_],  g_hL[ROWS_*C_];      // LN out
__device__ __align__(16) __half g_wqTH[H_*DH_*C_], g_wqTL[H_*DH_*C_];
__device__ __align__(16) __half g_wkTH[H_*DH_*C_], g_wkTL[H_*DH_*C_];
__device__ __align__(16) __half g_wvTH[H_*DH_*C_], g_wvTL[H_*DH_*C_];
__device__ __align__(16) __half g_w1TH[C_*DFF_],   g_w1TL[C_*DFF_];   // [Dff][C]
__device__ __align__(16) __half g_w2TH[C_*DFF_],   g_w2TL[C_*DFF_];   // [C][Dff]
__device__ __align__(16) __half g_qH[ROWS_*C_],  g_qL[ROWS_*C_];      // [B,H,T,Dh]
__device__ __align__(16) __half g_kH[ROWS_*C_],  g_kL[ROWS_*C_];
__device__ __align__(16) __half g_vH[ROWS_*C_],  g_vL[ROWS_*C_];
__device__ __align__(16) __half g_vtH[ROWS_*C_], g_vtL[ROWS_*C_];     // [B,H,Dh,T]
__device__ __align__(16) __half g_ff1H[(long)ROWS_*DFF_], g_ff1L[(long)ROWS_*DFF_];
__device__ float g_xmid[ROWS_*C_];

// ---------------- helpers ----------------
__device__ __forceinline__ void fsplit(float v, __half& hi, __half& lo) {
    hi = __float2half_rn(v);
    lo = __float2half_rn(v - __half2float(hi));
}

__device__ __forceinline__ void ldsm4(u32 addr, u32& r0, u32& r1, u32& r2, u32& r3) {
    asm volatile("ldmatrix.sync.aligned.m8n8.x4.shared.b16 {%0,%1,%2,%3}, [%4];"
                 : "=r"(r0), "=r"(r1), "=r"(r2), "=r"(r3) : "r"(addr));
}

__device__ __forceinline__ void mma16(float* c, const u32* a, const u32* b) {
    asm("mma.sync.aligned.m16n8k16.row.col.f32.f16.f16.f32 "
        "{%0,%1,%2,%3}, {%4,%5,%6,%7}, {%8,%9}, {%0,%1,%2,%3};\n"
        : "+f"(c[0]), "+f"(c[1]), "+f"(c[2]), "+f"(c[3])
        : "r"(a[0]), "r"(a[1]), "r"(a[2]), "r"(a[3]), "r"(b[0]), "r"(b[1]));
}

__device__ __forceinline__ void cp16h(__half* smem_dst, const __half* gmem_src) {
    u32 s = (u32)__cvta_generic_to_shared(smem_dst);
    asm volatile("cp.async.cg.shared.global [%0], [%1], 16;\n" :: "r"(s), "l"(gmem_src));
}

// pack two fp32 into half2 hi-word + lo-word (compensated split)
__device__ __forceinline__ u32 packsplit(float v0, float v1, u32& lo) {
    __half a = __float2half_rn(v0), b = __float2half_rn(v1);
    __half al = __float2half_rn(v0 - __half2float(a));
    __half bl = __float2half_rn(v1 - __half2float(b));
    lo = (u32)__half_as_ushort(al) | ((u32)__half_as_ushort(bl) << 16);
    return (u32)__half_as_ushort(a) | ((u32)__half_as_ushort(b) << 16);
}

// ---------------- LayerNorm -> fp16 hi/lo ----------------
__global__ __launch_bounds__(256) void ln_split_kernel(
    const float* __restrict__ x, const float* __restrict__ g,
    const float* __restrict__ b, __half* __restrict__ oh, __half* __restrict__ ol)
{
    long row = blockIdx.x;
    const float* p = x + row * C_;
    int tid = threadIdx.x;
    float v[4];
    float s = 0.f, s2 = 0.f;
    #pragma unroll
    for (int i = 0; i < 4; i++) {
        v[i] = p[tid + i*256];
        s += v[i]; s2 += v[i]*v[i];
    }
    __shared__ float sh[2][8];
    #pragma unroll
    for (int o = 16; o; o >>= 1) {
        s  += __shfl_xor_sync(0xffffffffu, s,  o);
        s2 += __shfl_xor_sync(0xffffffffu, s2, o);
    }
    int lane = tid & 31, w = tid >> 5;
    if (lane == 0) { sh[0][w] = s; sh[1][w] = s2; }
    __syncthreads();
    if (tid == 0) {
        float a = 0.f, c = 0.f;
        #pragma unroll
        for (int i = 0; i < 8; i++) { a += sh[0][i]; c += sh[1][i]; }
        sh[0][0] = a; sh[1][0] = c;
    }
    __syncthreads();
    float mu  = sh[0][0] * (1.f / C_);
    float var = sh[1][0] * (1.f / C_) - mu * mu;
    float rstd = rsqrtf(var + 1e-5f);
    #pragma unroll
    for (int i = 0; i < 4; i++) {
        int n = tid + i*256;
        float o = (v[i] - mu) * rstd * g[n] + b[n];
        __half hi, lo; fsplit(o, hi, lo);
        oh[row * C_ + n] = hi;
        ol[row * C_ + n] = lo;
    }
}

// ---------------- transpose fp32 -> split fp16 hi/lo ----------------
__global__ __launch_bounds__(256) void tr_split32_kernel(
    const float* __restrict__ in, __half* __restrict__ oh, __half* __restrict__ ol,
    int R, int Cc)
{
    long zo = (long)blockIdx.z * R * Cc;
    in += zo; oh += zo; ol += zo;
    __shared__ float t[32][33];
    int c0 = blockIdx.x * 32, r0 = blockIdx.y * 32;
    int tid = threadIdx.x;
    int tx = tid & 31, ty = tid >> 5;
    #pragma unroll
    for (int j = 0; j < 4; j++)
        t[ty + j*8][tx] = in[(long)(r0 + ty + j*8) * Cc + c0 + tx];
    __syncthreads();
    #pragma unroll
    for (int j = 0; j < 4; j++) {
        float v = t[tx][ty + j*8];
        __half hi, lo; fsplit(v, hi, lo);
        long idx = (long)(c0 + ty + j*8) * R + r0 + tx;
        oh[idx] = hi; ol[idx] = lo;
    }
}

// ---------------- transpose fp16 pair ----------------
__global__ __launch_bounds__(256) void tr_pair16_kernel(
    const __half* __restrict__ ih, const __half* __restrict__ il,
    __half* __restrict__ oh, __half* __restrict__ ol, int R, int Cc)
{
    long zo = (long)blockIdx.z * R * Cc;
    ih += zo; il += zo; oh += zo; ol += zo;
    __shared__ __half th[32][34];
    __shared__ __half tl[32][34];
    int c0 = blockIdx.x * 32, r0 = blockIdx.y * 32;
    int tid = threadIdx.x;
    int tx = tid & 31, ty = tid >> 5;
    #pragma unroll
    for (int j = 0; j < 4; j++) {
        long idx = (long)(r0 + ty + j*8) * Cc + c0 + tx;
        th[ty + j*8][tx] = ih[idx];
        tl[ty + j*8][tx] = il[idx];
    }
    __syncthreads();
    #pragma unroll
    for (int j = 0; j < 4; j++) {
        long idx = (long)(c0 + ty + j*8) * R + r0 + tx;
        oh[idx] = th[tx][ty + j*8];
        ol[idx] = tl[tx][ty + j*8];
    }
}

// ---------------- fused flash attention ----------------
// One CTA = 128 q rows of one (b,h). Q,K,V hi/lo in smem (FLD=136 halves/row).
// 8 warps x 16 rows, warp-local online softmax, 3-term compensated MMA both stages.
#define FLD 136
#define FTILE (128*FLD)                 // halves per array
#define SM_FLASH (6*FTILE*2)            // 208896 bytes

__global__ __launch_bounds__(256, 1) void flash_kernel(
    const __half* __restrict__ qH, const __half* __restrict__ qL,
    const __half* __restrict__ kH, const __half* __restrict__ kL,
    const __half* __restrict__ vtH, const __half* __restrict__ vtL,
    const float* __restrict__ x, float* __restrict__ xmid)
{
    extern __shared__ __half sm[];
    __half* sQh = sm;
    __half* sQl = sm + FTILE;
    __half* sKh = sm + 2*FTILE;
    __half* sKl = sm + 3*FTILE;
    __half* sVh = sm + 4*FTILE;
    __half* sVl = sm + 5*FTILE;

    const int bh = blockIdx.z;
    const int b  = bh >> 3;             // H_ = 8
    const int h  = bh & 7;
    const int q0 = blockIdx.y * 128;

    const long hoff = (long)bh * T_ * DH_;
    const __half* qHh = qH + hoff + (long)q0 * DH_;
    const __half* qLl = qL + hoff + (long)q0 * DH_;
    const __half* kHh = kH + hoff;
    const __half* kLl = kL + hoff;
    const __half* vHh = vtH + hoff;     // [Dh][T]
    const __half* vLl = vtL + hoff;

    const int tid  = threadIdx.x;
    const int lane = tid & 31;
    const int warp = tid >> 5;
    const int g = lane >> 2, t = lane & 3;
    const int w16 = warp * 16;

    const int lrow = tid >> 1;          // 0..127
    const int lcol = (tid & 1) * 64;    // 0 / 64 halves

    // ---- prologue loads: Q | K0 | V0 (three cp.async groups) ----
    #pragma unroll
    for (int c = 0; c < 8; c++) {
        cp16h(&sQh[lrow*FLD + lcol + c*8], &qHh[lrow*DH_ + lcol + c*8]);
        cp16h(&sQl[lrow*FLD + lcol + c*8], &qLl[lrow*DH_ + lcol + c*8]);
    }
    asm volatile("cp.async.commit_group;\n");
    #pragma unroll
    for (int c = 0; c < 8; c++) {
        cp16h(&sKh[lrow*FLD + lcol + c*8], &kHh[lrow*DH_ + lcol + c*8]);
        cp16h(&sKl[lrow*FLD + lcol + c*8], &kLl[lrow*DH_ + lcol + c*8]);
    }
    asm volatile("cp.async.commit_group;\n");
    #pragma unroll
    for (int c = 0; c < 8; c++) {
        cp16h(&sVh[lrow*FLD + lcol + c*8], &vHh[(long)lrow*T_ + lcol + c*8]);
        cp16h(&sVl[lrow*FLD + lcol + c*8], &vLl[(long)lrow*T_ + lcol + c*8]);
    }
    asm volatile("cp.async.commit_group;\n");

    const u32 QhU = (u32)__cvta_generic_to_shared(sQh);
    const u32 QlU = (u32)__cvta_generic_to_shared(sQl);
    const u32 KhU = (u32)__cvta_generic_to_shared(sKh);
    const u32 KlU = (u32)__cvta_generic_to_shared(sKl);
    const u32 VhU = (u32)__cvta_generic_to_shared(sVh);
    const u32 VlU = (u32)__cvta_generic_to_shared(sVl);
    const u32 laneRow = (u32)((lane & 15) * (FLD*2) + ((lane >> 4) & 1) * 16);

    float oacc[16][4];
    #pragma unroll
    for (int i = 0; i < 16; i++)
        #pragma unroll
        for (int j = 0; j < 4; j++) oacc[i][j] = 0.f;
    float m0r = -1e30f, m1r = -1e30f, l0r = 0.f, l1r = 0.f;
    const float scale = 11.3137084989847604f;   // sqrt(128)

    asm volatile("cp.async.wait_group 1;\n");   // Q + K0 done (V0 in flight)
    __syncthreads();

    for (int s = 0; s < 16; s++) {
        // ---- S = Q @ K_s^T ----
        float sacc[16][4];
        #pragma unroll
        for (int i = 0; i < 16; i++)
            #pragma unroll
            for (int j = 0; j < 4; j++) sacc[i][j] = 0.f;

        for (int kc = 0; kc < 8; kc++) {
            const u32 ko = laneRow + (u32)(kc * 32);
            u32 ah[4], al[4];
            ldsm4(QhU + (u32)(w16 * (FLD*2)) + ko, ah[0], ah[1], ah[2], ah[3]);
            ldsm4(QlU + (u32)(w16 * (FLD*2)) + ko, al[0], al[1], al[2], al[3]);
            #pragma unroll
            for (int p = 0; p < 8; p++) {
                u32 r0, r1, r2, r3, s0, s1, s2, s3;
                ldsm4(KhU + (u32)(p * 16 * (FLD*2)) + ko, r0, r1, r2, r3);
                ldsm4(KlU + (u32)(p * 16 * (FLD*2)) + ko, s0, s1, s2, s3);
                u32 bh0[2] = {r0, r2}, bh1[2] = {r1, r3};
                u32 bl0[2] = {s0, s2}, bl1[2] = {s1, s3};
                mma16(sacc[2*p],   ah, bh0);  mma16(sacc[2*p+1], ah, bh1);
                mma16(sacc[2*p],   al, bh0);  mma16(sacc[2*p+1], al, bh1);
                mma16(sacc[2*p],   ah, bl0);  mma16(sacc[2*p+1], ah, bl1);
            }
        }
        __syncthreads();                         // all warps done with K_s
        if (s < 15) {                            // prefetch K_{s+1}
            const __half* kh = kHh + (long)((s+1)*128 + lrow) * DH_ + lcol;
            const __half* kl = kLl + (long)((s+1)*128 + lrow) * DH_ + lcol;
            #pragma unroll
            for (int c = 0; c < 8; c++) {
                cp16h(&sKh[lrow*FLD + lcol + c*8], kh + c*8);
                cp16h(&sKl[lrow*FLD + lcol + c*8], kl + c*8);
            }
            asm volatile("cp.async.commit_group;\n");
        }

        // ---- online softmax (warp-local, rows g / g+8) ----
        #pragma unroll
        for (int i = 0; i < 16; i++)
            #pragma unroll
            for (int j = 0; j < 4; j++) sacc[i][j] *= scale;

        float rx0 = -1e30f, rx1 = -1e30f;
        #pragma unroll
        for (int i = 0; i < 16; i++) {
            rx0 = fmaxf(rx0, fmaxf(sacc[i][0], sacc[i][1]));
            rx1 = fmaxf(rx1, fmaxf(sacc[i][2], sacc[i][3]));
        }
        rx0 = fmaxf(rx0, __shfl_xor_sync(0xffffffffu, rx0, 1));
        rx0 = fmaxf(rx0, __shfl_xor_sync(0xffffffffu, rx0, 2));
        rx1 = fmaxf(rx1, __shfl_xor_sync(0xffffffffu, rx1, 1));
        rx1 = fmaxf(rx1, __shfl_xor_sync(0xffffffffu, rx1, 2));
        float mn0 = fmaxf(m0r, rx0), mn1 = fmaxf(m1r, rx1);
        float cor0 = __expf(m0r - mn0), cor1 = __expf(m1r - mn1);
        m0r = mn0; m1r = mn1;
        #pragma unroll
        for (int i = 0; i < 16; i++) {
            oacc[i][0] *= cor0; oacc[i][1] *= cor0;
            oacc[i][2] *= cor1; oacc[i][3] *= cor1;
        }
        float rs0 = 0.f, rs1 = 0.f;
        #pragma unroll
        for (int i = 0; i < 16; i++) {
            sacc[i][0] = __expf(sacc[i][0] - mn0);
            sacc[i][1] = __expf(sacc[i][1] - mn0);
            sacc[i][2] = __expf(sacc[i][2] - mn1);
            sacc[i][3] = __expf(sacc[i][3] - mn1);
            rs0 += sacc[i][0] + sacc[i][1];
            rs1 += sacc[i][2] + sacc[i][3];
        }
        rs0 += __shfl_xor_sync(0xffffffffu, rs0, 1);
        rs0 += __shfl_xor_sync(0xffffffffu, rs0, 2);
        rs1 += __shfl_xor_sync(0xffffffffu, rs1, 1);
        rs1 += __shfl_xor_sync(0xffffffffu, rs1, 2);
        l0r = l0r * cor0 + rs0;
        l1r = l1r * cor1 + rs1;

        // ---- wait V_s, then O += P @ V_s ----
        if (s < 15) { asm volatile("cp.async.wait_group 1;\n"); }
        else        { asm volatile("cp.async.wait_group 0;\n"); }
        __syncthreads();

        #pragma unroll
        for (int j = 0; j < 8; j++) {
            u32 ph[4], pl[4];
            ph[0] = packsplit(sacc[2*j][0],   sacc[2*j][1],   pl[0]);
            ph[1] = packsplit(sacc[2*j][2],   sacc[2*j][3],   pl[1]);
            ph[2] = packsplit(sacc[2*j+1][0], sacc[2*j+1][1], pl[2]);
            ph[3] = packsplit(sacc[2*j+1][2], sacc[2*j+1][3], pl[3]);
            const u32 jo = laneRow + (u32)(j * 32);
            #pragma unroll
            for (int p = 0; p < 8; p++) {
                u32 r0, r1, r2, r3, s0, s1, s2, s3;
                ldsm4(VhU + (u32)(p * 16 * (FLD*2)) + jo, r0, r1, r2, r3);
                ldsm4(VlU + (u32)(p * 16 * (FLD*2)) + jo, s0, s1, s2, s3);
                u32 bh0[2] = {r0, r2}, bh1[2] = {r1, r3};
                u32 bl0[2] = {s0, s2}, bl1[2] = {s1, s3};
                mma16(oacc[2*p],   ph, bh0);  mma16(oacc[2*p+1], ph, bh1);
                mma16(oacc[2*p],   pl, bh0);  mma16(oacc[2*p+1], pl, bh1);
                mma16(oacc[2*p],   ph, bl0);  mma16(oacc[2*p+1], ph, bl1);
            }
        }

        if (s < 15) {
            __syncthreads();                     // all warps done with V_s
            const __half* vh = vHh + (long)lrow * T_ + (s+1)*128 + lcol;
            const __half* vl = vLl + (long)lrow * T_ + (s+1)*128 + lcol;
            #pragma unroll
            for (int c = 0; c < 8; c++) {
                cp16h(&sVh[lrow*FLD + lcol + c*8], vh + c*8);
                cp16h(&sVl[lrow*FLD + lcol + c*8], vl + c*8);
            }
            asm volatile("cp.async.commit_group;\n");
            asm volatile("cp.async.wait_group 1;\n");   // K_{s+1} done
            __syncthreads();
        }
    }

    // ---- epilogue: O/l + residual x -> xmid ----
    const float i0 = 1.f / l0r, i1 = 1.f / l1r;
    const int rg = q0 + w16 + g;
    const long base0 = ((long)b * T_ + rg) * C_ + h * DH_;
    const long base1 = base0 + 8L * C_;
    #pragma unroll
    for (int nt = 0; nt < 16; nt++) {
        int col = 8 * nt + 2 * t;
        float2 xv0 = *(const float2*)&x[base0 + col];
        float2 o0;
        o0.x = xv0.x + oacc[nt][0] * i0;
        o0.y = xv0.y + oacc[nt][1] * i0;
        *(float2*)&xmid[base0 + col] = o0;
        float2 xv1 = *(const float2*)&x[base1 + col];
        float2 o1;
        o1.x = xv1.x + oacc[nt][2] * i1;
        o1.y = xv1.y + oacc[nt][3] * i1;
        *(float2*)&xmid[base1 + col] = o1;
    }
}

// ---------------- 3xFP16 tensor-core batched GEMM ----------------
#define SLD 24
#define TILEH (128*SLD)

template<bool RELU, bool BIAS, bool RES, bool F16OUT>
__global__ __launch_bounds__(256, 2) void hgemm3_kernel(
    int K,
    const __half* __restrict__ Ahp, const __half* __restrict__ Alp, int lda, long sAb, long sAh,
    const __half* __restrict__ Bhp, const __half* __restrict__ Blp, int ldb, long sBb, long sBh,
    float* __restrict__ Cf, __half* __restrict__ Ch, __half* __restrict__ Cl,
    int ldc, long sCb, long sCh,
    const float* __restrict__ bias,
    const float* __restrict__ res, int ldr, long sRb, long sRh,
    float alpha, int H)
{
    int z = blockIdx.z;
    int zb = z / H, zh = z - zb * H;
    Ahp += zb * sAb + zh * sAh;  Alp += zb * sAb + zh * sAh;
    Bhp += zb * sBb + zh * sBh;  Blp += zb * sBb + zh * sBh;
    long co = zb * sCb + zh * sCh;
    if (F16OUT) { Ch += co; Cl += co; } else { Cf += co; }
    if (RES) res += zb * sRb + zh * sRh;

    __shared__ __align__(16) __half smb[2 * 4 * TILEH];

    const int m0 = blockIdx.y * 128;
    const int n0 = blockIdx.x * 128;
    const int tid  = threadIdx.x;
    const int lane = tid & 31;
    const int warp = tid >> 5;
    const int mwarp = (warp >> 2) * 64;
    const int nwarp = (warp & 3) * 32;
    const int g = lane >> 2;
    const int t = lane & 3;

    float acc[16][4];
    #pragma unroll
    for (int i = 0; i < 16; i++)
        #pragma unroll
        for (int j = 0; j < 4; j++) acc[i][j] = 0.f;

    const int ldrow = tid >> 1;
    const int ldseg = (tid & 1) * 8;

    auto issue_loads = [&](int k0, int buf) {
        __half* base = smb + buf * 4 * TILEH;
        int so = ldrow * SLD + ldseg;
        cp16h(base + so,             Ahp + (long)(m0 + ldrow) * lda + k0 + ldseg);
        cp16h(base + TILEH + so,     Alp + (long)(m0 + ldrow) * lda + k0 + ldseg);
        cp16h(base + 2*TILEH + so,   Bhp + (long)(n0 + ldrow) * ldb + k0 + ldseg);
        cp16h(base + 3*TILEH + so,   Blp + (long)(n0 + ldrow) * ldb + k0 + ldseg);
        asm volatile("cp.async.commit_group;\n");
    };

    const u32 smemU = (u32)__cvta_generic_to_shared(smb);
    const u32 laneOff = (u32)((lane & 15) * (SLD * 2) + ((lane >> 4) & 1) * 16);

    issue_loads(0, 0);
    const int nIter = K / 16;

    for (int i = 0; i < nIter; i++) {
        asm volatile("cp.async.wait_group 0;\n");
        __syncthreads();
        if (i + 1 < nIter) issue_loads((i + 1) * 16, (i + 1) & 1);

        const u32 sb = smemU + (u32)((i & 1) * 4 * TILEH * 2);
        const u32 aH = sb;
        const u32 aL = sb + TILEH * 2;
        const u32 bH = sb + 2 * TILEH * 2;
        const u32 bL = sb + 3 * TILEH * 2;

        u32 ah[4][4], al[4][4], bh[4][2], bl[4][2];
        #pragma unroll
        for (int p = 0; p < 2; p++) {
            u32 r0, r1, r2, r3;
            u32 off = (u32)((nwarp + p * 16) * (SLD * 2)) + laneOff;
            ldsm4(bH + off, r0, r1, r2, r3);
            bh[2*p][0] = r0; bh[2*p+1][0] = r1; bh[2*p][1] = r2; bh[2*p+1][1] = r3;
            ldsm4(bL + off, r0, r1, r2, r3);
            bl[2*p][0] = r0; bl[2*p+1][0] = r1; bl[2*p][1] = r2; bl[2*p+1][1] = r3;
        }
        #pragma unroll
        for (int mt = 0; mt < 4; mt++) {
            u32 off = (u32)((mwarp + mt * 16) * (SLD * 2)) + laneOff;
            ldsm4(aH + off, ah[mt][0], ah[mt][1], ah[mt][2], ah[mt][3]);
            ldsm4(aL + off, al[mt][0], al[mt][1], al[mt][2], al[mt][3]);
        }

        #pragma unroll
        for (int mt = 0; mt < 4; mt++)
            #pragma unroll
            for (int nt = 0; nt < 4; nt++)
                mma16(acc[mt * 4 + nt], ah[mt], bh[nt]);
        #pragma unroll
        for (int mt = 0; mt < 4; mt++)
            #pragma unroll
            for (int nt = 0; nt < 4; nt++)
                mma16(acc[mt * 4 + nt], al[mt], bh[nt]);
        #pragma unroll
        for (int mt = 0; mt < 4; mt++)
            #pragma unroll
            for (int nt = 0; nt < 4; nt++)
                mma16(acc[mt * 4 + nt], ah[mt], bl[nt]);
        __syncthreads();
    }

    #pragma unroll
    for (int mt = 0; mt < 4; mt++) {
        #pragma unroll
        for (int nt = 0; nt < 4; nt++) {
            const float* a4 = acc[mt * 4 + nt];
            int rr = m0 + mwarp + mt * 16 + g;
            int cc = n0 + nwarp + nt * 8 + 2 * t;
            #pragma unroll
            for (int half = 0; half < 2; half++) {
                int m = rr + half * 8;
                float v0 = a4[half * 2 + 0] * alpha;
                float v1 = a4[half * 2 + 1] * alpha;
                if (BIAS) { v0 += bias[cc]; v1 += bias[cc + 1]; }
                if (RELU) { v0 = fmaxf(v0, 0.f); v1 = fmaxf(v1, 0.f); }
                if (RES) {
                    v0 += res[(long)m * ldr + cc];
                    v1 += res[(long)m * ldr + cc + 1];
                }
                if (F16OUT) {
                    __half h0, l0, h1, l1;
                    fsplit(v0, h0, l0); fsplit(v1, h1, l1);
                    *reinterpret_cast<__half2*>(&Ch[(long)m * ldc + cc]) = __halves2half2(h0, h1);
                    *reinterpret_cast<__half2*>(&Cl[(long)m * ldc + cc]) = __halves2half2(l0, l1);
                } else {
                    Cf[(long)m * ldc + cc]     = v0;
                    Cf[(long)m * ldc + cc + 1] = v1;
                }
            }
        }
    }
}

// ---------------- launch ----------------
extern "C" void kernel_launch(void* const* d_in, const int* in_sizes, int n_in,
                              void* d_out, int out_size)
{
    const float* x     = (const float*)d_in[0];
    const float* wq    = (const float*)d_in[1];
    const float* wk    = (const float*)d_in[2];
    const float* wv    = (const float*)d_in[3];
    const float* w1    = (const float*)d_in[4];
    const float* b1    = (const float*)d_in[5];
    const float* w2    = (const float*)d_in[6];
    const float* b2    = (const float*)d_in[7];
    const float* ln1_g = (const float*)d_in[8];
    const float* ln1_b = (const float*)d_in[9];
    const float* ln2_g = (const float*)d_in[10];
    const float* ln2_b = (const float*)d_in[11];
    float* out = (float*)d_out;

    __half *hH,*hL, *wqTH,*wqTL, *wkTH,*wkTL, *wvTH,*wvTL, *w1TH,*w1TL, *w2TH,*w2TL;
    __half *qH,*qL, *kH,*kL, *vH,*vL, *vtH,*vtL, *f1H,*f1L;
    float *xmid;
    cudaGetSymbolAddress((void**)&hH, g_hH);   cudaGetSymbolAddress((void**)&hL, g_hL);
    cudaGetSymbolAddress((void**)&wqTH, g_wqTH); cudaGetSymbolAddress((void**)&wqTL, g_wqTL);
    cudaGetSymbolAddress((void**)&wkTH, g_wkTH); cudaGetSymbolAddress((void**)&wkTL, g_wkTL);
    cudaGetSymbolAddress((void**)&wvTH, g_wvTH); cudaGetSymbolAddress((void**)&wvTL, g_wvTL);
    cudaGetSymbolAddress((void**)&w1TH, g_w1TH); cudaGetSymbolAddress((void**)&w1TL, g_w1TL);
    cudaGetSymbolAddress((void**)&w2TH, g_w2TH); cudaGetSymbolAddress((void**)&w2TL, g_w2TL);
    cudaGetSymbolAddress((void**)&qH, g_qH);   cudaGetSymbolAddress((void**)&qL, g_qL);
    cudaGetSymbolAddress((void**)&kH, g_kH);   cudaGetSymbolAddress((void**)&kL, g_kL);
    cudaGetSymbolAddress((void**)&vH, g_vH);   cudaGetSymbolAddress((void**)&vL, g_vL);
    cudaGetSymbolAddress((void**)&vtH, g_vtH); cudaGetSymbolAddress((void**)&vtL, g_vtL);
    cudaGetSymbolAddress((void**)&f1H, g_ff1H); cudaGetSymbolAddress((void**)&f1L, g_ff1L);
    cudaGetSymbolAddress((void**)&xmid, g_xmid);

    cudaFuncSetAttribute(flash_kernel, cudaFuncAttributeMaxDynamicSharedMemorySize, SM_FLASH);

    const long HTD  = (long)T_ * DH_;
    const long BTD  = (long)H_ * HTD;
    const long TC   = (long)T_ * C_;

    // ---- weight pre-pass ----
    tr_split32_kernel<<<dim3(DH_/32, C_/32, H_), 256>>>(wq, wqTH, wqTL, C_, DH_);
    tr_split32_kernel<<<dim3(DH_/32, C_/32, H_), 256>>>(wk, wkTH, wkTL, C_, DH_);
    tr_split32_kernel<<<dim3(DH_/32, C_/32, H_), 256>>>(wv, wvTH, wvTL, C_, DH_);
    tr_split32_kernel<<<dim3(DFF_/32, C_/32, 1), 256>>>(w1, w1TH, w1TL, C_, DFF_);
    tr_split32_kernel<<<dim3(C_/32, DFF_/32, 1), 256>>>(w2, w2TH, w2TL, DFF_, C_);

    // ---- LN1 ----
    ln_split_kernel<<<ROWS_, 256>>>(x, ln1_g, ln1_b, hH, hL);

    // ---- QKV ----
    dim3 gq(1, T_/128, B_*H_);
    hgemm3_kernel<false,false,false,true><<<gq, 256>>>(
        C_, hH, hL, C_, TC, 0,  wqTH, wqTL, C_, 0, (long)DH_*C_,
        nullptr, qH, qL, DH_, BTD, HTD,  nullptr, nullptr, 0, 0, 0, 1.f, H_);
    hgemm3_kernel<false,false,false,true><<<gq, 256>>>(
        C_, hH, hL, C_, TC, 0,  wkTH, wkTL, C_, 0, (long)DH_*C_,
        nullptr, kH, kL, DH_, BTD, HTD,  nullptr, nullptr, 0, 0, 0, 1.f, H_);
    hgemm3_kernel<false,false,false,true><<<gq, 256>>>(
        C_, hH, hL, C_, TC, 0,  wvTH, wvTL, C_, 0, (long)DH_*C_,
        nullptr, vH, vL, DH_, BTD, HTD,  nullptr, nullptr, 0, 0, 0, 1.f, H_);

    // ---- V^T per (b,h): [T][Dh] -> [Dh][T] ----
    tr_pair16_kernel<<<dim3(DH_/32, T_/32, B_*H_), 256>>>(vH, vL, vtH, vtL, T_, DH_);

    // ---- fused flash attention (+ x residual) -> xmid ----
    flash_kernel<<<dim3(1, T_/128, B_*H_), 256, SM_FLASH>>>(
        qH, qL, kH, kL, vtH, vtL, x, xmid);

    // ---- LN2 ----
    ln_split_kernel<<<ROWS_, 256>>>(xmid, ln2_g, ln2_b, hH, hL);

    // ---- FF1 ----
    dim3 g1(DFF_/128, ROWS_/128, 1);
    hgemm3_kernel<true,true,false,true><<<g1, 256>>>(
        C_, hH, hL, C_, 0, 0,  w1TH, w1TL, C_, 0, 0,
        nullptr, f1H, f1L, DFF_, 0, 0,  b1, nullptr, 0, 0, 0, 1.f, 1);

    // ---- FF2 ----
    dim3 g2(C_/128, ROWS_/128, 1);
    hgemm3_kernel<false,true,true,false><<<g2, 256>>>(
        DFF_, f1H, f1L, DFF_, 0, 0,  w2TH, w2TL, DFF_, 0, 0,
        out, nullptr, nullptr, C_, 0, 0,  b2, xmid, C_, 0, 0, 1.f, 1);
}

// round 12
// speedup vs baseline: 1.5657x; 1.5657x over previous
#include <cuda_runtime.h>
#include <cuda_fp16.h>
#include <math.h>

// ---------------- problem dims ----------------
#define B_  4
#define T_  2048
#define C_  1024
#define H_  8
#define DH_ 128
#define DFF_ 4096
#define ROWS_ (B_*T_)          // 8192

typedef unsigned int u32;

// ---------------- scratch (device globals; no allocs allowed) ----------------
__device__ __align__(16) __half g_hH[ROWS_*C_],  g_hL[ROWS_*C_];          // LN out
__device__ __align__(16) __half g_wqkvTH[3*C_*C_], g_wqkvTL[3*C_*C_];     // [3072][1024]
__device__ __align__(16) __half g_w1TH[C_*DFF_],   g_w1TL[C_*DFF_];       // [Dff][C]
__device__ __align__(16) __half g_w2TH[C_*DFF_],   g_w2TL[C_*DFF_];       // [C][Dff]
__device__ __align__(16) __half g_qH[ROWS_*C_],  g_qL[ROWS_*C_];          // [B,H,T,Dh]
__device__ __align__(16) __half g_kH[ROWS_*C_],  g_kL[ROWS_*C_];
__device__ __align__(16) __half g_vH[ROWS_*C_],  g_vL[ROWS_*C_];
__device__ __align__(16) __half g_vtH[ROWS_*C_], g_vtL[ROWS_*C_];         // [B,H,Dh,T]
__device__ float g_scores[(long)B_*H_*T_*T_];
__device__ __align__(16) __half g_pH[(long)B_*H_*T_*T_];                  // probs (fp16 only)
__device__ __align__(16) __half g_ff1H[(long)ROWS_*DFF_], g_ff1L[(long)ROWS_*DFF_];
__device__ float g_xmid[ROWS_*C_];

// ---------------- helpers ----------------
__device__ __forceinline__ void fsplit(float v, __half& hi, __half& lo) {
    hi = __float2half_rn(v);
    lo = __float2half_rn(v - __half2float(hi));
}
__device__ __forceinline__ void ldsm4(u32 addr, u32& r0, u32& r1, u32& r2, u32& r3) {
    asm volatile("ldmatrix.sync.aligned.m8n8.x4.shared.b16 {%0,%1,%2,%3}, [%4];"
                 : "=r"(r0), "=r"(r1), "=r"(r2), "=r"(r3) : "r"(addr));
}
__device__ __forceinline__ void mma16(float* c, const u32* a, const u32* b) {
    asm("mma.sync.aligned.m16n8k16.row.col.f32.f16.f16.f32 "
        "{%0,%1,%2,%3}, {%4,%5,%6,%7}, {%8,%9}, {%0,%1,%2,%3};\n"
        : "+f"(c[0]), "+f"(c[1]), "+f"(c[2]), "+f"(c[3])
        : "r"(a[0]), "r"(a[1]), "r"(a[2]), "r"(a[3]), "r"(b[0]), "r"(b[1]));
}
__device__ __forceinline__ void cp16h(__half* smem_dst, const __half* gmem_src) {
    u32 s = (u32)__cvta_generic_to_shared(smem_dst);
    asm volatile("cp.async.cg.shared.global [%0], [%1], 16;\n" :: "r"(s), "l"(gmem_src));
}

// ---------------- LayerNorm -> fp16 hi/lo ----------------
__global__ __launch_bounds__(256) void ln_split_kernel(
    const float* __restrict__ x, const float* __restrict__ g,
    const float* __restrict__ b, __half* __restrict__ oh, __half* __restrict__ ol)
{
    long row = blockIdx.x;
    const float* p = x + row * C_;
    int tid = threadIdx.x;
    float v[4];
    float s = 0.f, s2 = 0.f;
    #pragma unroll
    for (int i = 0; i < 4; i++) {
        v[i] = p[tid + i*256];
        s += v[i]; s2 += v[i]*v[i];
    }
    __shared__ float sh[2][8];
    #pragma unroll
    for (int o = 16; o; o >>= 1) {
        s  += __shfl_xor_sync(0xffffffffu, s,  o);
        s2 += __shfl_xor_sync(0xffffffffu, s2, o);
    }
    int lane = tid & 31, w = tid >> 5;
    if (lane == 0) { sh[0][w] = s; sh[1][w] = s2; }
    __syncthreads();
    if (tid == 0) {
        float a = 0.f, c = 0.f;
        #pragma unroll
        for (int i = 0; i < 8; i++) { a += sh[0][i]; c += sh[1][i]; }
        sh[0][0] = a; sh[1][0] = c;
    }
    __syncthreads();
    float mu  = sh[0][0] * (1.f / C_);
    float var = sh[1][0] * (1.f / C_) - mu * mu;
    float rstd = rsqrtf(var + 1e-5f);
    #pragma unroll
    for (int i = 0; i < 4; i++) {
        int n = tid + i*256;
        float o = (v[i] - mu) * rstd * g[n] + b[n];
        __half hi, lo; fsplit(o, hi, lo);
        oh[row * C_ + n] = hi;
        ol[row * C_ + n] = lo;
    }
}

// ---------------- Softmax -> fp16 probs (hi only) ----------------
__global__ __launch_bounds__(256) void softmax_h_kernel(
    const float* __restrict__ sc, __half* __restrict__ ph)
{
    long row = blockIdx.x;
    const float* p = sc + row * (long)T_;
    int tid = threadIdx.x;
    float v[8];
    float m = -1e30f;
    #pragma unroll
    for (int i = 0; i < 8; i++) { v[i] = p[tid + i*256]; m = fmaxf(m, v[i]); }
    __shared__ float sh[8];
    __shared__ float res;
    int lane = tid & 31, w = tid >> 5;
    #pragma unroll
    for (int o = 16; o; o >>= 1) m = fmaxf(m, __shfl_xor_sync(0xffffffffu, m, o));
    if (lane == 0) sh[w] = m;
    __syncthreads();
    if (tid == 0) {
        float a = sh[0];
        #pragma unroll
        for (int i = 1; i < 8; i++) a = fmaxf(a, sh[i]);
        res = a;
    }
    __syncthreads();
    float mm = res;
    float sum = 0.f;
    #pragma unroll
    for (int i = 0; i < 8; i++) { v[i] = __expf(v[i] - mm); sum += v[i]; }
    __syncthreads();
    #pragma unroll
    for (int o = 16; o; o >>= 1) sum += __shfl_xor_sync(0xffffffffu, sum, o);
    if (lane == 0) sh[w] = sum;
    __syncthreads();
    if (tid == 0) {
        float a = 0.f;
        #pragma unroll
        for (int i = 0; i < 8; i++) a += sh[i];
        res = a;
    }
    __syncthreads();
    float inv = 1.f / res;
    #pragma unroll
    for (int i = 0; i < 8; i++)
        ph[row * (long)T_ + tid + i*256] = __float2half_rn(v[i] * inv);
}

// ---------------- transpose fp32 -> split fp16 hi/lo ----------------
__global__ __launch_bounds__(256) void tr_split32_kernel(
    const float* __restrict__ in, __half* __restrict__ oh, __half* __restrict__ ol,
    int R, int Cc)
{
    long zo = (long)blockIdx.z * R * Cc;
    in += zo; oh += zo; ol += zo;
    __shared__ float t[32][33];
    int c0 = blockIdx.x * 32, r0 = blockIdx.y * 32;
    int tid = threadIdx.x;
    int tx = tid & 31, ty = tid >> 5;
    #pragma unroll
    for (int j = 0; j < 4; j++)
        t[ty + j*8][tx] = in[(long)(r0 + ty + j*8) * Cc + c0 + tx];
    __syncthreads();
    #pragma unroll
    for (int j = 0; j < 4; j++) {
        float v = t[tx][ty + j*8];
        __half hi, lo; fsplit(v, hi, lo);
        long idx = (long)(c0 + ty + j*8) * R + r0 + tx;
        oh[idx] = hi; ol[idx] = lo;
    }
}

// ---------------- transpose fp16 pair ----------------
__global__ __launch_bounds__(256) void tr_pair16_kernel(
    const __half* __restrict__ ih, const __half* __restrict__ il,
    __half* __restrict__ oh, __half* __restrict__ ol, int R, int Cc)
{
    long zo = (long)blockIdx.z * R * Cc;
    ih += zo; il += zo; oh += zo; ol += zo;
    __shared__ __half th[32][34];
    __shared__ __half tl[32][34];
    int c0 = blockIdx.x * 32, r0 = blockIdx.y * 32;
    int tid = threadIdx.x;
    int tx = tid & 31, ty = tid >> 5;
    #pragma unroll
    for (int j = 0; j < 4; j++) {
        long idx = (long)(r0 + ty + j*8) * Cc + c0 + tx;
        th[ty + j*8][tx] = ih[idx];
        tl[ty + j*8][tx] = il[idx];
    }
    __syncthreads();
    #pragma unroll
    for (int j = 0; j < 4; j++) {
        long idx = (long)(c0 + ty + j*8) * R + r0 + tx;
        oh[idx] = th[tx][ty + j*8];
        ol[idx] = tl[tx][ty + j*8];
    }
}

// ---------------- compensated FP16 tensor-core batched GEMM ----------------
// C[m,n] = alpha * sum_k A[m,k] * B[n,k]  (both K-major fp16; A hi/lo iff ALO)
// 128x128 CTA tile, BK=16, 8 warps of 64x32, 4-stage cp.async pipeline.
// OUT: 0 = fp32 (+bias/relu/res), 1 = fp16 hi/lo pair, 2 = QKV scatter.
#define SLD 24
#define TILEH (128*SLD)
#define NSTG 4

template<bool ALO, bool RELU, bool BIAS, bool RES, int OUT>
__global__ __launch_bounds__(256, 2) void hgemm_kernel(
    int K,
    const __half* __restrict__ Ahp, const __half* __restrict__ Alp, int lda, long sAb, long sAh,
    const __half* __restrict__ Bhp, const __half* __restrict__ Blp, int ldb, long sBb, long sBh,
    float* __restrict__ Cf, __half* __restrict__ Ch, __half* __restrict__ Cl,
    int ldc, long sCb, long sCh,
    const float* __restrict__ bias,
    const float* __restrict__ res, int ldr, long sRb, long sRh,
    float alpha, int Hn,
    __half* __restrict__ kvH1, __half* __restrict__ kvL1,
    __half* __restrict__ kvH2, __half* __restrict__ kvL2)
{
    constexpr int NARR = ALO ? 4 : 3;
    extern __shared__ __half dsm[];

    int z = blockIdx.z;
    int zb = z / Hn, zh = z - zb * Hn;
    Ahp += zb * sAb + zh * sAh;
    if (ALO) Alp += zb * sAb + zh * sAh;
    Bhp += zb * sBb + zh * sBh;  Blp += zb * sBb + zh * sBh;
    long co = zb * sCb + zh * sCh;
    if (OUT == 0) Cf += co; else if (OUT == 1) { Ch += co; Cl += co; }
    if (RES) res += zb * sRb + zh * sRh;

    const int m0 = blockIdx.y * 128;
    const int n0 = blockIdx.x * 128;
    const int tid  = threadIdx.x;
    const int lane = tid & 31;
    const int warp = tid >> 5;
    const int mwarp = (warp >> 2) * 64;
    const int nwarp = (warp & 3) * 32;
    const int g = lane >> 2;
    const int t = lane & 3;

    float acc[16][4];
    #pragma unroll
    for (int i = 0; i < 16; i++)
        #pragma unroll
        for (int j = 0; j < 4; j++) acc[i][j] = 0.f;

    const int ldrow = tid >> 1;
    const int ldseg = (tid & 1) * 8;
    const int nIter = K / 16;

    auto issue = [&](int it) {
        __half* base = dsm + (it & (NSTG-1)) * NARR * TILEH;
        int so = ldrow * SLD + ldseg;
        int k0 = it * 16;
        cp16h(base + so, Ahp + (long)(m0 + ldrow) * lda + k0 + ldseg);
        if (ALO) cp16h(base + TILEH + so, Alp + (long)(m0 + ldrow) * lda + k0 + ldseg);
        cp16h(base + (NARR-2)*TILEH + so, Bhp + (long)(n0 + ldrow) * ldb + k0 + ldseg);
        cp16h(base + (NARR-1)*TILEH + so, Blp + (long)(n0 + ldrow) * ldb + k0 + ldseg);
        asm volatile("cp.async.commit_group;\n");
    };

    const u32 smemU = (u32)__cvta_generic_to_shared(dsm);
    const u32 laneOff = (u32)((lane & 15) * (SLD * 2) + ((lane >> 4) & 1) * 16);

    issue(0); issue(1); issue(2);    // nIter >= 8 for all call sites

    for (int i = 0; i < nIter; i++) {
        asm volatile("cp.async.wait_group 2;\n");
        __syncthreads();
        if (i + 3 < nIter) issue(i + 3);
        else asm volatile("cp.async.commit_group;\n");   // keep group count invariant

        const u32 sb = smemU + (u32)((i & (NSTG-1)) * NARR * TILEH * 2);
        const u32 aH = sb;
        const u32 aL = sb + TILEH * 2;
        const u32 bH = sb + (NARR-2) * TILEH * 2;
        const u32 bL = sb + (NARR-1) * TILEH * 2;

        u32 ah[4][4], al[4][4], bh[4][2], bl[4][2];
        #pragma unroll
        for (int p = 0; p < 2; p++) {
            u32 r0, r1, r2, r3;
            u32 off = (u32)((nwarp + p * 16) * (SLD * 2)) + laneOff;
            ldsm4(bH + off, r0, r1, r2, r3);
            bh[2*p][0] = r0; bh[2*p+1][0] = r1; bh[2*p][1] = r2; bh[2*p+1][1] = r3;
            ldsm4(bL + off, r0, r1, r2, r3);
            bl[2*p][0] = r0; bl[2*p+1][0] = r1; bl[2*p][1] = r2; bl[2*p+1][1] = r3;
        }
        #pragma unroll
        for (int mt = 0; mt < 4; mt++) {
            u32 off = (u32)((mwarp + mt * 16) * (SLD * 2)) + laneOff;
            ldsm4(aH + off, ah[mt][0], ah[mt][1], ah[mt][2], ah[mt][3]);
            if (ALO) ldsm4(aL + off, al[mt][0], al[mt][1], al[mt][2], al[mt][3]);
        }

        #pragma unroll
        for (int mt = 0; mt < 4; mt++)
            #pragma unroll
            for (int nt = 0; nt < 4; nt++)
                mma16(acc[mt * 4 + nt], ah[mt], bh[nt]);   // hi*hi
        if (ALO) {
            #pragma unroll
            for (int mt = 0; mt < 4; mt++)
                #pragma unroll
                for (int nt = 0; nt < 4; nt++)
                    mma16(acc[mt * 4 + nt], al[mt], bh[nt]);   // lo*hi
        }
        #pragma unroll
        for (int mt = 0; mt < 4; mt++)
            #pragma unroll
            for (int nt = 0; nt < 4; nt++)
                mma16(acc[mt * 4 + nt], ah[mt], bl[nt]);   // hi*lo
    }

    // ---- epilogue ----
    int qsel = 0, qh = 0;
    __half *dH = Ch, *dL = Cl;
    if (OUT == 2) {
        qsel = n0 >> 10;
        qh   = (n0 >> 7) & 7;
        dH = (qsel == 0) ? Ch : (qsel == 1) ? kvH1 : kvH2;
        dL = (qsel == 0) ? Cl : (qsel == 1) ? kvL1 : kvL2;
    }
    #pragma unroll
    for (int mt = 0; mt < 4; mt++) {
        #pragma unroll
        for (int nt = 0; nt < 4; nt++) {
            const float* a4 = acc[mt * 4 + nt];
            int rr = m0 + mwarp + mt * 16 + g;
            int cc = n0 + nwarp + nt * 8 + 2 * t;
            #pragma unroll
            for (int half = 0; half < 2; half++) {
                int m = rr + half * 8;
                float v0 = a4[half * 2 + 0] * alpha;
                float v1 = a4[half * 2 + 1] * alpha;
                if (BIAS) { v0 += bias[cc]; v1 += bias[cc + 1]; }
                if (RELU) { v0 = fmaxf(v0, 0.f); v1 = fmaxf(v1, 0.f); }
                if (RES) {
                    v0 += res[(long)m * ldr + cc];
                    v1 += res[(long)m * ldr + cc + 1];
                }
                if (OUT == 0) {
                    Cf[(long)m * ldc + cc]     = v0;
                    Cf[(long)m * ldc + cc + 1] = v1;
                } else if (OUT == 1) {
                    __half h0, l0, h1, l1;
                    fsplit(v0, h0, l0); fsplit(v1, h1, l1);
                    *reinterpret_cast<__half2*>(&Ch[(long)m * ldc + cc]) = __halves2half2(h0, h1);
                    *reinterpret_cast<__half2*>(&Cl[(long)m * ldc + cc]) = __halves2half2(l0, l1);
                } else {
                    long base = (((long)(m >> 11) * 8 + qh) * 2048 + (m & 2047)) * 128 + (cc & 127);
                    __half h0, l0, h1, l1;
                    fsplit(v0, h0, l0); fsplit(v1, h1, l1);
                    *reinterpret_cast<__half2*>(&dH[base]) = __halves2half2(h0, h1);
                    *reinterpret_cast<__half2*>(&dL[base]) = __halves2half2(l0, l1);
                }
            }
        }
    }
}

#define SMEM_ALO (NSTG * 4 * TILEH * 2)   // 98304
#define SMEM_NA  (NSTG * 3 * TILEH * 2)   // 73728

// ---------------- launch ----------------
extern "C" void kernel_launch(void* const* d_in, const int* in_sizes, int n_in,
                              void* d_out, int out_size)
{
    const float* x     = (const float*)d_in[0];
    const float* wq    = (const float*)d_in[1];
    const float* wk    = (const float*)d_in[2];
    const float* wv    = (const float*)d_in[3];
    const float* w1    = (const float*)d_in[4];
    const float* b1    = (const float*)d_in[5];
    const float* w2    = (const float*)d_in[6];
    const float* b2    = (const float*)d_in[7];
    const float* ln1_g = (const float*)d_in[8];
    const float* ln1_b = (const float*)d_in[9];
    const float* ln2_g = (const float*)d_in[10];
    const float* ln2_b = (const float*)d_in[11];
    float* out = (float*)d_out;

    __half *hH,*hL, *wqkvTH,*wqkvTL, *w1TH,*w1TL, *w2TH,*w2TL;
    __half *qH,*qL, *kH,*kL, *vH,*vL, *vtH,*vtL, *pH, *f1H,*f1L;
    float *sc, *xmid;
    cudaGetSymbolAddress((void**)&hH, g_hH);   cudaGetSymbolAddress((void**)&hL, g_hL);
    cudaGetSymbolAddress((void**)&wqkvTH, g_wqkvTH); cudaGetSymbolAddress((void**)&wqkvTL, g_wqkvTL);
    cudaGetSymbolAddress((void**)&w1TH, g_w1TH); cudaGetSymbolAddress((void**)&w1TL, g_w1TL);
    cudaGetSymbolAddress((void**)&w2TH, g_w2TH); cudaGetSymbolAddress((void**)&w2TL, g_w2TL);
    cudaGetSymbolAddress((void**)&qH, g_qH);   cudaGetSymbolAddress((void**)&qL, g_qL);
    cudaGetSymbolAddress((void**)&kH, g_kH);   cudaGetSymbolAddress((void**)&kL, g_kL);
    cudaGetSymbolAddress((void**)&vH, g_vH);   cudaGetSymbolAddress((void**)&vL, g_vL);
    cudaGetSymbolAddress((void**)&vtH, g_vtH); cudaGetSymbolAddress((void**)&vtL, g_vtL);
    cudaGetSymbolAddress((void**)&pH, g_pH);
    cudaGetSymbolAddress((void**)&f1H, g_ff1H); cudaGetSymbolAddress((void**)&f1L, g_ff1L);
    cudaGetSymbolAddress((void**)&sc, g_scores);
    cudaGetSymbolAddress((void**)&xmid, g_xmid);

    cudaFuncSetAttribute(hgemm_kernel<true,false,false,false,2>,
                         cudaFuncAttributeMaxDynamicSharedMemorySize, SMEM_ALO);
    cudaFuncSetAttribute(hgemm_kernel<true,false,false,false,0>,
                         cudaFuncAttributeMaxDynamicSharedMemorySize, SMEM_ALO);
    cudaFuncSetAttribute(hgemm_kernel<false,false,false,true,0>,
                         cudaFuncAttributeMaxDynamicSharedMemorySize, SMEM_NA);
    cudaFuncSetAttribute(hgemm_kernel<true,true,true,false,1>,
                         cudaFuncAttributeMaxDynamicSharedMemorySize, SMEM_ALO);
    cudaFuncSetAttribute(hgemm_kernel<true,false,true,true,0>,
                         cudaFuncAttributeMaxDynamicSharedMemorySize, SMEM_ALO);

    const float scale = 11.3137084989847604f;  // sqrt(128)
    const long HTD  = (long)T_ * DH_;
    const long BTD  = (long)H_ * HTD;
    const long STT  = (long)T_ * T_;
    const long SBB  = (long)H_ * STT;
    const long TC   = (long)T_ * C_;

    // ---- weight pre-pass: wq/wk/wv -> concatenated [3072][1024]; w1T, w2T ----
    tr_split32_kernel<<<dim3(DH_/32, C_/32, H_), 256>>>(wq, wqkvTH,           wqkvTL,           C_, DH_);
    tr_split32_kernel<<<dim3(DH_/32, C_/32, H_), 256>>>(wk, wqkvTH + C_*C_,   wqkvTL + C_*C_,   C_, DH_);
    tr_split32_kernel<<<dim3(DH_/32, C_/32, H_), 256>>>(wv, wqkvTH + 2*C_*C_, wqkvTL + 2*C_*C_, C_, DH_);
    tr_split32_kernel<<<dim3(DFF_/32, C_/32, 1), 256>>>(w1, w1TH, w1TL, C_, DFF_);
    tr_split32_kernel<<<dim3(C_/32, DFF_/32, 1), 256>>>(w2, w2TH, w2TL, DFF_, C_);

    // ---- LN1 ----
    ln_split_kernel<<<ROWS_, 256>>>(x, ln1_g, ln1_b, hH, hL);

    // ---- fused QKV: [8192x1024] @ [3072x1024]^T, scatter to q/k/v ----
    hgemm_kernel<true,false,false,false,2><<<dim3(3*C_/128, ROWS_/128, 1), 256, SMEM_ALO>>>(
        C_, hH, hL, C_, 0, 0,  wqkvTH, wqkvTL, C_, 0, 0,
        nullptr, qH, qL, 0, 0, 0,  nullptr, nullptr, 0, 0, 0, 1.f, 1,
        kH, kL, vH, vL);

    // ---- V^T per (b,h): [T][Dh] -> [Dh][T] ----
    tr_pair16_kernel<<<dim3(DH_/32, T_/32, B_*H_), 256>>>(vH, vL, vtH, vtL, T_, DH_);

    // ---- scores = Q @ K^T * sqrt(Dh) ----
    hgemm_kernel<true,false,false,false,0><<<dim3(T_/128, T_/128, B_*H_), 256, SMEM_ALO>>>(
        DH_, qH, qL, DH_, BTD, HTD,  kH, kL, DH_, BTD, HTD,
        sc, nullptr, nullptr, T_, SBB, STT,  nullptr, nullptr, 0, 0, 0, scale, H_,
        nullptr, nullptr, nullptr, nullptr);

    // ---- softmax -> probs fp16 ----
    softmax_h_kernel<<<B_*H_*T_, 256>>>(sc, pH);

    // ---- O = P @ V (+x residual) -> xmid;  P single, V hi/lo (2-term) ----
    hgemm_kernel<false,false,false,true,0><<<dim3(1, T_/128, B_*H_), 256, SMEM_NA>>>(
        T_, pH, nullptr, T_, SBB, STT,  vtH, vtL, T_, BTD, HTD,
        xmid, nullptr, nullptr, C_, TC, DH_,  nullptr, x, C_, TC, DH_, 1.f, H_,
        nullptr, nullptr, nullptr, nullptr);

    // ---- LN2 ----
    ln_split_kernel<<<ROWS_, 256>>>(xmid, ln2_g, ln2_b, hH, hL);

    // ---- FF1: relu(h @ w1 + b1) -> fp16 hi/lo ----
    hgemm_kernel<true,true,true,false,1><<<dim3(DFF_/128, ROWS_/128, 1), 256, SMEM_ALO>>>(
        C_, hH, hL, C_, 0, 0,  w1TH, w1TL, C_, 0, 0,
        nullptr, f1H, f1L, DFF_, 0, 0,  b1, nullptr, 0, 0, 0, 1.f, 1,
        nullptr, nullptr, nullptr, nullptr);

    // ---- FF2: out = xmid + ff1 @ w2 + b2 ----
    hgemm_kernel<true,false,true,true,0><<<dim3(C_/128, ROWS_/128, 1), 256, SMEM_ALO>>>(
        DFF_, f1H, f1L, DFF_, 0, 0,  w2TH, w2TL, DFF_, 0, 0,
        out, nullptr, nullptr, C_, 0, 0,  b2, xmid, C_, 0, 0, 1.f, 1,
        nullptr, nullptr, nullptr, nullptr);
}

// round 13
// speedup vs baseline: 1.9069x; 1.2180x over previous
#include <cuda_runtime.h>
#include <cuda_fp16.h>
#include <math.h>

// ---------------- problem dims ----------------
#define B_  4
#define T_  2048
#define C_  1024
#define H_  8
#define DH_ 128
#define DFF_ 4096
#define ROWS_ (B_*T_)          // 8192

typedef unsigned int u32;

// ---------------- scratch (device globals; no allocs allowed) ----------------
__device__ __align__(16) __half g_hH[ROWS_*C_],  g_hL[ROWS_*C_];          // LN out
__device__ __align__(16) __half g_wqkvTH[3*C_*C_], g_wqkvTL[3*C_*C_];     // [3072][1024]
__device__ __align__(16) __half g_w1TH[C_*DFF_],   g_w1TL[C_*DFF_];       // [Dff][C]
__device__ __align__(16) __half g_w2TH[C_*DFF_],   g_w2TL[C_*DFF_];       // [C][Dff]
__device__ __align__(16) __half g_qH[ROWS_*C_],  g_qL[ROWS_*C_];          // [B,H,T,Dh]
__device__ __align__(16) __half g_kH[ROWS_*C_],  g_kL[ROWS_*C_];
__device__ __align__(16) __half g_vH[ROWS_*C_],  g_vL[ROWS_*C_];
__device__ __align__(16) __half g_vtH[ROWS_*C_], g_vtL[ROWS_*C_];         // [B,H,Dh,T]
__device__ float g_scores[(long)B_*H_*T_*T_];
__device__ __align__(16) __half g_pH[(long)B_*H_*T_*T_];                  // probs (fp16 only)
__device__ __align__(16) __half g_ff1H[(long)ROWS_*DFF_];                 // ff1 (fp16 only)
__device__ float g_xmid[ROWS_*C_];

// ---------------- helpers ----------------
__device__ __forceinline__ void fsplit(float v, __half& hi, __half& lo) {
    hi = __float2half_rn(v);
    lo = __float2half_rn(v - __half2float(hi));
}
__device__ __forceinline__ void ldsm4(u32 addr, u32& r0, u32& r1, u32& r2, u32& r3) {
    asm volatile("ldmatrix.sync.aligned.m8n8.x4.shared.b16 {%0,%1,%2,%3}, [%4];"
                 : "=r"(r0), "=r"(r1), "=r"(r2), "=r"(r3) : "r"(addr));
}
__device__ __forceinline__ void mma16(float* c, const u32* a, const u32* b) {
    asm("mma.sync.aligned.m16n8k16.row.col.f32.f16.f16.f32 "
        "{%0,%1,%2,%3}, {%4,%5,%6,%7}, {%8,%9}, {%0,%1,%2,%3};\n"
        : "+f"(c[0]), "+f"(c[1]), "+f"(c[2]), "+f"(c[3])
        : "r"(a[0]), "r"(a[1]), "r"(a[2]), "r"(a[3]), "r"(b[0]), "r"(b[1]));
}
__device__ __forceinline__ void cp16h(__half* smem_dst, const __half* gmem_src) {
    u32 s = (u32)__cvta_generic_to_shared(smem_dst);
    asm volatile("cp.async.cg.shared.global [%0], [%1], 16;\n" :: "r"(s), "l"(gmem_src));
}

// ---------------- LayerNorm -> fp16 hi/lo ----------------
__global__ __launch_bounds__(256) void ln_split_kernel(
    const float* __restrict__ x, const float* __restrict__ g,
    const float* __restrict__ b, __half* __restrict__ oh, __half* __restrict__ ol)
{
    long row = blockIdx.x;
    const float* p = x + row * C_;
    int tid = threadIdx.x;
    float v[4];
    float s = 0.f, s2 = 0.f;
    #pragma unroll
    for (int i = 0; i < 4; i++) {
        v[i] = p[tid + i*256];
        s += v[i]; s2 += v[i]*v[i];
    }
    __shared__ float sh[2][8];
    #pragma unroll
    for (int o = 16; o; o >>= 1) {
        s  += __shfl_xor_sync(0xffffffffu, s,  o);
        s2 += __shfl_xor_sync(0xffffffffu, s2, o);
    }
    int lane = tid & 31, w = tid >> 5;
    if (lane == 0) { sh[0][w] = s; sh[1][w] = s2; }
    __syncthreads();
    if (tid == 0) {
        float a = 0.f, c = 0.f;
        #pragma unroll
        for (int i = 0; i < 8; i++) { a += sh[0][i]; c += sh[1][i]; }
        sh[0][0] = a; sh[1][0] = c;
    }
    __syncthreads();
    float mu  = sh[0][0] * (1.f / C_);
    float var = sh[1][0] * (1.f / C_) - mu * mu;
    float rstd = rsqrtf(var + 1e-5f);
    #pragma unroll
    for (int i = 0; i < 4; i++) {
        int n = tid + i*256;
        float o = (v[i] - mu) * rstd * g[n] + b[n];
        __half hi, lo; fsplit(o, hi, lo);
        oh[row * C_ + n] = hi;
        ol[row * C_ + n] = lo;
    }
}

// ---------------- Softmax -> fp16 probs (hi only) ----------------
__global__ __launch_bounds__(256) void softmax_h_kernel(
    const float* __restrict__ sc, __half* __restrict__ ph)
{
    long row = blockIdx.x;
    const float* p = sc + row * (long)T_;
    int tid = threadIdx.x;
    float v[8];
    float m = -1e30f;
    #pragma unroll
    for (int i = 0; i < 8; i++) { v[i] = p[tid + i*256]; m = fmaxf(m, v[i]); }
    __shared__ float sh[8];
    __shared__ float res;
    int lane = tid & 31, w = tid >> 5;
    #pragma unroll
    for (int o = 16; o; o >>= 1) m = fmaxf(m, __shfl_xor_sync(0xffffffffu, m, o));
    if (lane == 0) sh[w] = m;
    __syncthreads();
    if (tid == 0) {
        float a = sh[0];
        #pragma unroll
        for (int i = 1; i < 8; i++) a = fmaxf(a, sh[i]);
        res = a;
    }
    __syncthreads();
    float mm = res;
    float sum = 0.f;
    #pragma unroll
    for (int i = 0; i < 8; i++) { v[i] = __expf(v[i] - mm); sum += v[i]; }
    __syncthreads();
    #pragma unroll
    for (int o = 16; o; o >>= 1) sum += __shfl_xor_sync(0xffffffffu, sum, o);
    if (lane == 0) sh[w] = sum;
    __syncthreads();
    if (tid == 0) {
        float a = 0.f;
        #pragma unroll
        for (int i = 0; i < 8; i++) a += sh[i];
        res = a;
    }
    __syncthreads();
    float inv = 1.f / res;
    #pragma unroll
    for (int i = 0; i < 8; i++)
        ph[row * (long)T_ + tid + i*256] = __float2half_rn(v[i] * inv);
}

// ---------------- transpose fp32 -> split fp16 hi/lo ----------------
__global__ __launch_bounds__(256) void tr_split32_kernel(
    const float* __restrict__ in, __half* __restrict__ oh, __half* __restrict__ ol,
    int R, int Cc)
{
    long zo = (long)blockIdx.z * R * Cc;
    in += zo; oh += zo; ol += zo;
    __shared__ float t[32][33];
    int c0 = blockIdx.x * 32, r0 = blockIdx.y * 32;
    int tid = threadIdx.x;
    int tx = tid & 31, ty = tid >> 5;
    #pragma unroll
    for (int j = 0; j < 4; j++)
        t[ty + j*8][tx] = in[(long)(r0 + ty + j*8) * Cc + c0 + tx];
    __syncthreads();
    #pragma unroll
    for (int j = 0; j < 4; j++) {
        float v = t[tx][ty + j*8];
        __half hi, lo; fsplit(v, hi, lo);
        long idx = (long)(c0 + ty + j*8) * R + r0 + tx;
        oh[idx] = hi; ol[idx] = lo;
    }
}

// ---------------- transpose fp16 pair ----------------
__global__ __launch_bounds__(256) void tr_pair16_kernel(
    const __half* __restrict__ ih, const __half* __restrict__ il,
    __half* __restrict__ oh, __half* __restrict__ ol, int R, int Cc)
{
    long zo = (long)blockIdx.z * R * Cc;
    ih += zo; il += zo; oh += zo; ol += zo;
    __shared__ __half th[32][34];
    __shared__ __half tl[32][34];
    int c0 = blockIdx.x * 32, r0 = blockIdx.y * 32;
    int tid = threadIdx.x;
    int tx = tid & 31, ty = tid >> 5;
    #pragma unroll
    for (int j = 0; j < 4; j++) {
        long idx = (long)(r0 + ty + j*8) * Cc + c0 + tx;
        th[ty + j*8][tx] = ih[idx];
        tl[ty + j*8][tx] = il[idx];
    }
    __syncthreads();
    #pragma unroll
    for (int j = 0; j < 4; j++) {
        long idx = (long)(c0 + ty + j*8) * R + r0 + tx;
        oh[idx] = th[tx][ty + j*8];
        ol[idx] = tl[tx][ty + j*8];
    }
}

// ---------------- compensated FP16 tensor-core batched GEMM ----------------
// C[m,n] = alpha * sum_k A[m,k] * B[n,k]  (K-major fp16)
// Terms: hi*hi always; lo_A*hi_B iff ALO; hi_A*lo_B iff BLO.
// 128x128 CTA tile, BK=16, 8 warps of 64x32, 4-stage cp.async pipeline.
// OUT: 0 = fp32 (+bias/relu/res), 1 = fp16 hi/lo pair, 2 = QKV scatter, 3 = fp16 hi.
#define SLD 24
#define TILEH (128*SLD)
#define NSTG 4

template<bool ALO, bool BLO, bool RELU, bool BIAS, bool RES, int OUT>
__global__ __launch_bounds__(256, 2) void hgemm_kernel(
    int K,
    const __half* __restrict__ Ahp, const __half* __restrict__ Alp, int lda, long sAb, long sAh,
    const __half* __restrict__ Bhp, const __half* __restrict__ Blp, int ldb, long sBb, long sBh,
    float* __restrict__ Cf, __half* __restrict__ Ch, __half* __restrict__ Cl,
    int ldc, long sCb, long sCh,
    const float* __restrict__ bias,
    const float* __restrict__ res, int ldr, long sRb, long sRh,
    float alpha, int Hn,
    __half* __restrict__ kvH1, __half* __restrict__ kvL1,
    __half* __restrict__ kvH2, __half* __restrict__ kvL2)
{
    constexpr int NARR = 2 + (ALO ? 1 : 0) + (BLO ? 1 : 0);
    extern __shared__ __half dsm[];

    int z = blockIdx.z;
    int zb = z / Hn, zh = z - zb * Hn;
    Ahp += zb * sAb + zh * sAh;
    if (ALO) Alp += zb * sAb + zh * sAh;
    Bhp += zb * sBb + zh * sBh;
    if (BLO) Blp += zb * sBb + zh * sBh;
    long co = zb * sCb + zh * sCh;
    if (OUT == 0) Cf += co; else if (OUT == 1 || OUT == 3) { Ch += co; if (OUT == 1) Cl += co; }
    if (RES) res += zb * sRb + zh * sRh;

    const int m0 = blockIdx.y * 128;
    const int n0 = blockIdx.x * 128;
    const int tid  = threadIdx.x;
    const int lane = tid & 31;
    const int warp = tid >> 5;
    const int mwarp = (warp >> 2) * 64;
    const int nwarp = (warp & 3) * 32;
    const int g = lane >> 2;
    const int t = lane & 3;

    float acc[16][4];
    #pragma unroll
    for (int i = 0; i < 16; i++)
        #pragma unroll
        for (int j = 0; j < 4; j++) acc[i][j] = 0.f;

    const int ldrow = tid >> 1;
    const int ldseg = (tid & 1) * 8;
    const int nIter = K / 16;

    constexpr int BH_IDX = 1 + (ALO ? 1 : 0);          // index of B_hi array
    constexpr int BL_IDX = BH_IDX + 1;                 // index of B_lo array (if BLO)

    auto issue = [&](int it) {
        __half* base = dsm + (it & (NSTG-1)) * NARR * TILEH;
        int so = ldrow * SLD + ldseg;
        int k0 = it * 16;
        cp16h(base + so, Ahp + (long)(m0 + ldrow) * lda + k0 + ldseg);
        if (ALO) cp16h(base + TILEH + so, Alp + (long)(m0 + ldrow) * lda + k0 + ldseg);
        cp16h(base + BH_IDX*TILEH + so, Bhp + (long)(n0 + ldrow) * ldb + k0 + ldseg);
        if (BLO) cp16h(base + BL_IDX*TILEH + so, Blp + (long)(n0 + ldrow) * ldb + k0 + ldseg);
        asm volatile("cp.async.commit_group;\n");
    };

    const u32 smemU = (u32)__cvta_generic_to_shared(dsm);
    const u32 laneOff = (u32)((lane & 15) * (SLD * 2) + ((lane >> 4) & 1) * 16);

    issue(0); issue(1); issue(2);    // nIter >= 8 for all call sites

    for (int i = 0; i < nIter; i++) {
        asm volatile("cp.async.wait_group 2;\n");
        __syncthreads();
        if (i + 3 < nIter) issue(i + 3);
        else asm volatile("cp.async.commit_group;\n");   // keep group count invariant

        const u32 sb = smemU + (u32)((i & (NSTG-1)) * NARR * TILEH * 2);
        const u32 aH = sb;
        const u32 aL = sb + TILEH * 2;
        const u32 bH = sb + BH_IDX * TILEH * 2;
        const u32 bL = sb + BL_IDX * TILEH * 2;

        u32 ah[4][4], al[4][4], bh[4][2], bl[4][2];
        #pragma unroll
        for (int p = 0; p < 2; p++) {
            u32 r0, r1, r2, r3;
            u32 off = (u32)((nwarp + p * 16) * (SLD * 2)) + laneOff;
            ldsm4(bH + off, r0, r1, r2, r3);
            bh[2*p][0] = r0; bh[2*p+1][0] = r1; bh[2*p][1] = r2; bh[2*p+1][1] = r3;
            if (BLO) {
                ldsm4(bL + off, r0, r1, r2, r3);
                bl[2*p][0] = r0; bl[2*p+1][0] = r1; bl[2*p][1] = r2; bl[2*p+1][1] = r3;
            }
        }
        #pragma unroll
        for (int mt = 0; mt < 4; mt++) {
            u32 off = (u32)((mwarp + mt * 16) * (SLD * 2)) + laneOff;
            ldsm4(aH + off, ah[mt][0], ah[mt][1], ah[mt][2], ah[mt][3]);
            if (ALO) ldsm4(aL + off, al[mt][0], al[mt][1], al[mt][2], al[mt][3]);
        }

        #pragma unroll
        for (int mt = 0; mt < 4; mt++)
            #pragma unroll
            for (int nt = 0; nt < 4; nt++)
                mma16(acc[mt * 4 + nt], ah[mt], bh[nt]);   // hi*hi
        if (ALO) {
            #pragma unroll
            for (int mt = 0; mt < 4; mt++)
                #pragma unroll
                for (int nt = 0; nt < 4; nt++)
                    mma16(acc[mt * 4 + nt], al[mt], bh[nt]);   // lo*hi
        }
        if (BLO) {
            #pragma unroll
            for (int mt = 0; mt < 4; mt++)
                #pragma unroll
                for (int nt = 0; nt < 4; nt++)
                    mma16(acc[mt * 4 + nt], ah[mt], bl[nt]);   // hi*lo
        }
    }

    // ---- epilogue ----
    int qh = 0;
    __half *dH = Ch, *dL = Cl;
    if (OUT == 2) {
        int qsel = n0 >> 10;
        qh   = (n0 >> 7) & 7;
        dH = (qsel == 0) ? Ch : (qsel == 1) ? kvH1 : kvH2;
        dL = (qsel == 0) ? Cl : (qsel == 1) ? kvL1 : kvL2;
    }
    #pragma unroll
    for (int mt = 0; mt < 4; mt++) {
        #pragma unroll
        for (int nt = 0; nt < 4; nt++) {
            const float* a4 = acc[mt * 4 + nt];
            int rr = m0 + mwarp + mt * 16 + g;
            int cc = n0 + nwarp + nt * 8 + 2 * t;
            #pragma unroll
            for (int half = 0; half < 2; half++) {
                int m = rr + half * 8;
                float v0 = a4[half * 2 + 0] * alpha;
                float v1 = a4[half * 2 + 1] * alpha;
                if (BIAS) { v0 += bias[cc]; v1 += bias[cc + 1]; }
                if (RELU) { v0 = fmaxf(v0, 0.f); v1 = fmaxf(v1, 0.f); }
                if (RES) {
                    v0 += res[(long)m * ldr + cc];
                    v1 += res[(long)m * ldr + cc + 1];
                }
                if (OUT == 0) {
                    Cf[(long)m * ldc + cc]     = v0;
                    Cf[(long)m * ldc + cc + 1] = v1;
                } else if (OUT == 1) {
                    __half h0, l0, h1, l1;
                    fsplit(v0, h0, l0); fsplit(v1, h1, l1);
                    *reinterpret_cast<__half2*>(&Ch[(long)m * ldc + cc]) = __halves2half2(h0, h1);
                    *reinterpret_cast<__half2*>(&Cl[(long)m * ldc + cc]) = __halves2half2(l0, l1);
                } else if (OUT == 3) {
                    *reinterpret_cast<__half2*>(&Ch[(long)m * ldc + cc]) =
                        __halves2half2(__float2half_rn(v0), __float2half_rn(v1));
                } else {
                    long base = (((long)(m >> 11) * 8 + qh) * 2048 + (m & 2047)) * 128 + (cc & 127);
                    __half h0, l0, h1, l1;
                    fsplit(v0, h0, l0); fsplit(v1, h1, l1);
                    *reinterpret_cast<__half2*>(&dH[base]) = __halves2half2(h0, h1);
                    *reinterpret_cast<__half2*>(&dL[base]) = __halves2half2(l0, l1);
                }
            }
        }
    }
}

#define SMEM_4 (NSTG * 4 * TILEH * 2)   // 98304 (ALO && BLO)
#define SMEM_3 (NSTG * 3 * TILEH * 2)   // 73728 (one lo)

// ---------------- launch ----------------
extern "C" void kernel_launch(void* const* d_in, const int* in_sizes, int n_in,
                              void* d_out, int out_size)
{
    const float* x     = (const float*)d_in[0];
    const float* wq    = (const float*)d_in[1];
    const float* wk    = (const float*)d_in[2];
    const float* wv    = (const float*)d_in[3];
    const float* w1    = (const float*)d_in[4];
    const float* b1    = (const float*)d_in[5];
    const float* w2    = (const float*)d_in[6];
    const float* b2    = (const float*)d_in[7];
    const float* ln1_g = (const float*)d_in[8];
    const float* ln1_b = (const float*)d_in[9];
    const float* ln2_g = (const float*)d_in[10];
    const float* ln2_b = (const float*)d_in[11];
    float* out = (float*)d_out;

    __half *hH,*hL, *wqkvTH,*wqkvTL, *w1TH,*w1TL, *w2TH,*w2TL;
    __half *qH,*qL, *kH,*kL, *vH,*vL, *vtH,*vtL, *pH, *f1H;
    float *sc, *xmid;
    cudaGetSymbolAddress((void**)&hH, g_hH);   cudaGetSymbolAddress((void**)&hL, g_hL);
    cudaGetSymbolAddress((void**)&wqkvTH, g_wqkvTH); cudaGetSymbolAddress((void**)&wqkvTL, g_wqkvTL);
    cudaGetSymbolAddress((void**)&w1TH, g_w1TH); cudaGetSymbolAddress((void**)&w1TL, g_w1TL);
    cudaGetSymbolAddress((void**)&w2TH, g_w2TH); cudaGetSymbolAddress((void**)&w2TL, g_w2TL);
    cudaGetSymbolAddress((void**)&qH, g_qH);   cudaGetSymbolAddress((void**)&qL, g_qL);
    cudaGetSymbolAddress((void**)&kH, g_kH);   cudaGetSymbolAddress((void**)&kL, g_kL);
    cudaGetSymbolAddress((void**)&vH, g_vH);   cudaGetSymbolAddress((void**)&vL, g_vL);
    cudaGetSymbolAddress((void**)&vtH, g_vtH); cudaGetSymbolAddress((void**)&vtL, g_vtL);
    cudaGetSymbolAddress((void**)&pH, g_pH);
    cudaGetSymbolAddress((void**)&f1H, g_ff1H);
    cudaGetSymbolAddress((void**)&sc, g_scores);
    cudaGetSymbolAddress((void**)&xmid, g_xmid);

    cudaFuncSetAttribute(hgemm_kernel<true,true,false,false,false,2>,
                         cudaFuncAttributeMaxDynamicSharedMemorySize, SMEM_4);
    cudaFuncSetAttribute(hgemm_kernel<true,true,false,false,false,0>,
                         cudaFuncAttributeMaxDynamicSharedMemorySize, SMEM_4);
    cudaFuncSetAttribute(hgemm_kernel<false,true,false,false,true,0>,
                         cudaFuncAttributeMaxDynamicSharedMemorySize, SMEM_3);
    cudaFuncSetAttribute(hgemm_kernel<true,false,true,true,false,3>,
                         cudaFuncAttributeMaxDynamicSharedMemorySize, SMEM_3);
    cudaFuncSetAttribute(hgemm_kernel<false,true,false,true,true,0>,
                         cudaFuncAttributeMaxDynamicSharedMemorySize, SMEM_3);

    const float scale = 11.3137084989847604f;  // sqrt(128)
    const long HTD  = (long)T_ * DH_;
    const long BTD  = (long)H_ * HTD;
    const long STT  = (long)T_ * T_;
    const long SBB  = (long)H_ * STT;
    const long TC   = (long)T_ * C_;

    // ---- weight pre-pass: wq/wk/wv -> concatenated [3072][1024]; w1T, w2T ----
    tr_split32_kernel<<<dim3(DH_/32, C_/32, H_), 256>>>(wq, wqkvTH,           wqkvTL,           C_, DH_);
    tr_split32_kernel<<<dim3(DH_/32, C_/32, H_), 256>>>(wk, wqkvTH + C_*C_,   wqkvTL + C_*C_,   C_, DH_);
    tr_split32_kernel<<<dim3(DH_/32, C_/32, H_), 256>>>(wv, wqkvTH + 2*C_*C_, wqkvTL + 2*C_*C_, C_, DH_);
    tr_split32_kernel<<<dim3(DFF_/32, C_/32, 1), 256>>>(w1, w1TH, w1TL, C_, DFF_);
    tr_split32_kernel<<<dim3(C_/32, DFF_/32, 1), 256>>>(w2, w2TH, w2TL, DFF_, C_);

    // ---- LN1 ----
    ln_split_kernel<<<ROWS_, 256>>>(x, ln1_g, ln1_b, hH, hL);

    // ---- fused QKV (3-term): [8192x1024] @ [3072x1024]^T, scatter to q/k/v ----
    hgemm_kernel<true,true,false,false,false,2><<<dim3(3*C_/128, ROWS_/128, 1), 256, SMEM_4>>>(
        C_, hH, hL, C_, 0, 0,  wqkvTH, wqkvTL, C_, 0, 0,
        nullptr, qH, qL, 0, 0, 0,  nullptr, nullptr, 0, 0, 0, 1.f, 1,
        kH, kL, vH, vL);

    // ---- V^T per (b,h): [T][Dh] -> [Dh][T] ----
    tr_pair16_kernel<<<dim3(DH_/32, T_/32, B_*H_), 256>>>(vH, vL, vtH, vtL, T_, DH_);

    // ---- scores = Q @ K^T * sqrt(Dh) (3-term) ----
    hgemm_kernel<true,true,false,false,false,0><<<dim3(T_/128, T_/128, B_*H_), 256, SMEM_4>>>(
        DH_, qH, qL, DH_, BTD, HTD,  kH, kL, DH_, BTD, HTD,
        sc, nullptr, nullptr, T_, SBB, STT,  nullptr, nullptr, 0, 0, 0, scale, H_,
        nullptr, nullptr, nullptr, nullptr);

    // ---- softmax -> probs fp16 ----
    softmax_h_kernel<<<B_*H_*T_, 256>>>(sc, pH);

    // ---- O = P @ V (+x residual) -> xmid;  2-term (P single, V hi/lo) ----
    hgemm_kernel<false,true,false,false,true,0><<<dim3(1, T_/128, B_*H_), 256, SMEM_3>>>(
        T_, pH, nullptr, T_, SBB, STT,  vtH, vtL, T_, BTD, HTD,
        xmid, nullptr, nullptr, C_, TC, DH_,  nullptr, x, C_, TC, DH_, 1.f, H_,
        nullptr, nullptr, nullptr, nullptr);

    // ---- LN2 ----
    ln_split_kernel<<<ROWS_, 256>>>(xmid, ln2_g, ln2_b, hH, hL);

    // ---- FF1 (2-term: h hi/lo, w1 hi): relu(h @ w1 + b1) -> fp16 hi ----
    hgemm_kernel<true,false,true,true,false,3><<<dim3(DFF_/128, ROWS_/128, 1), 256, SMEM_3>>>(
        C_, hH, hL, C_, 0, 0,  w1TH, nullptr, C_, 0, 0,
        nullptr, f1H, nullptr, DFF_, 0, 0,  b1, nullptr, 0, 0, 0, 1.f, 1,
        nullptr, nullptr, nullptr, nullptr);

    // ---- FF2 (2-term: ff1 hi, w2 hi/lo): out = xmid + ff1 @ w2 + b2 ----
    hgemm_kernel<false,true,false,true,true,0><<<dim3(C_/128, ROWS_/128, 1), 256, SMEM_3>>>(
        DFF_, f1H, nullptr, DFF_, 0, 0,  w2TH, w2TL, DFF_, 0, 0,
        out, nullptr, nullptr, C_, 0, 0,  b2, xmid, C_, 0, 0, 1.f, 1,
        nullptr, nullptr, nullptr, nullptr);
}

// round 15
// speedup vs baseline: 2.0020x; 1.0499x over previous
#include <cuda_runtime.h>
#include <cuda_fp16.h>
#include <math.h>

// ---------------- problem dims ----------------
#define B_  4
#define T_  2048
#define C_  1024
#define H_  8
#define DH_ 128
#define DFF_ 4096
#define ROWS_ (B_*T_)          // 8192

typedef unsigned int u32;

// ---------------- scratch (device globals; no allocs allowed) ----------------
__device__ __align__(16) __half g_hH[ROWS_*C_],  g_hL[ROWS_*C_];          // LN out
__device__ __align__(16) __half g_wqkvTH[3*C_*C_], g_wqkvTL[3*C_*C_];     // [3072][1024]
__device__ __align__(16) __half g_w1TH[C_*DFF_],   g_w1TL[C_*DFF_];       // [Dff][C]
__device__ __align__(16) __half g_w2TH[C_*DFF_],   g_w2TL[C_*DFF_];       // [C][Dff]
__device__ __align__(16) __half g_qH[ROWS_*C_],  g_qL[ROWS_*C_];          // [B,H,T,Dh]
__device__ __align__(16) __half g_kH[ROWS_*C_],  g_kL[ROWS_*C_];
__device__ __align__(16) __half g_vH[ROWS_*C_],  g_vL[ROWS_*C_];
__device__ __align__(16) __half g_vtH[ROWS_*C_], g_vtL[ROWS_*C_];         // [B,H,Dh,T]
__device__ float g_scores[(long)B_*H_*T_*T_];
__device__ __align__(16) __half g_pH[(long)B_*H_*T_*T_];                  // probs (fp16 only)
__device__ __align__(16) __half g_ff1H[(long)ROWS_*DFF_];                 // ff1 (fp16 only)
__device__ float g_xmid[ROWS_*C_];

// ---------------- helpers ----------------
__device__ __forceinline__ void fsplit(float v, __half& hi, __half& lo) {
    hi = __float2half_rn(v);
    lo = __float2half_rn(v - __half2float(hi));
}
__device__ __forceinline__ void ldsm4(u32 addr, u32& r0, u32& r1, u32& r2, u32& r3) {
    asm volatile("ldmatrix.sync.aligned.m8n8.x4.shared.b16 {%0,%1,%2,%3}, [%4];"
                 : "=r"(r0), "=r"(r1), "=r"(r2), "=r"(r3) : "r"(addr));
}
__device__ __forceinline__ void mma16(float* c, const u32* a, const u32* b) {
    asm("mma.sync.aligned.m16n8k16.row.col.f32.f16.f16.f32 "
        "{%0,%1,%2,%3}, {%4,%5,%6,%7}, {%8,%9}, {%0,%1,%2,%3};\n"
        : "+f"(c[0]), "+f"(c[1]), "+f"(c[2]), "+f"(c[3])
        : "r"(a[0]), "r"(a[1]), "r"(a[2]), "r"(a[3]), "r"(b[0]), "r"(b[1]));
}
__device__ __forceinline__ void cp16h(__half* smem_dst, const __half* gmem_src) {
    u32 s = (u32)__cvta_generic_to_shared(smem_dst);
    asm volatile("cp.async.cg.shared.global [%0], [%1], 16;\n" :: "r"(s), "l"(gmem_src));
}

// ---------------- LayerNorm -> fp16 hi/lo ----------------
__global__ __launch_bounds__(256) void ln_split_kernel(
    const float* __restrict__ x, const float* __restrict__ g,
    const float* __restrict__ b, __half* __restrict__ oh, __half* __restrict__ ol)
{
    long row = blockIdx.x;
    const float* p = x + row * C_;
    int tid = threadIdx.x;
    float v[4];
    float s = 0.f, s2 = 0.f;
    #pragma unroll
    for (int i = 0; i < 4; i++) {
        v[i] = p[tid + i*256];
        s += v[i]; s2 += v[i]*v[i];
    }
    __shared__ float sh[2][8];
    #pragma unroll
    for (int o = 16; o; o >>= 1) {
        s  += __shfl_xor_sync(0xffffffffu, s,  o);
        s2 += __shfl_xor_sync(0xffffffffu, s2, o);
    }
    int lane = tid & 31, w = tid >> 5;
    if (lane == 0) { sh[0][w] = s; sh[1][w] = s2; }
    __syncthreads();
    if (tid == 0) {
        float a = 0.f, c = 0.f;
        #pragma unroll
        for (int i = 0; i < 8; i++) { a += sh[0][i]; c += sh[1][i]; }
        sh[0][0] = a; sh[1][0] = c;
    }
    __syncthreads();
    float mu  = sh[0][0] * (1.f / C_);
    float var = sh[1][0] * (1.f / C_) - mu * mu;
    float rstd = rsqrtf(var + 1e-5f);
    #pragma unroll
    for (int i = 0; i < 4; i++) {
        int n = tid + i*256;
        float o = (v[i] - mu) * rstd * g[n] + b[n];
        __half hi, lo; fsplit(o, hi, lo);
        oh[row * C_ + n] = hi;
        ol[row * C_ + n] = lo;
    }
}

// ---------------- Softmax -> fp16 probs (hi only) ----------------
__global__ __launch_bounds__(256) void softmax_h_kernel(
    const float* __restrict__ sc, __half* __restrict__ ph)
{
    long row = blockIdx.x;
    const float* p = sc + row * (long)T_;
    int tid = threadIdx.x;
    float v[8];
    float m = -1e30f;
    #pragma unroll
    for (int i = 0; i < 8; i++) { v[i] = p[tid + i*256]; m = fmaxf(m, v[i]); }
    __shared__ float sh[8];
    __shared__ float res;
    int lane = tid & 31, w = tid >> 5;
    #pragma unroll
    for (int o = 16; o; o >>= 1) m = fmaxf(m, __shfl_xor_sync(0xffffffffu, m, o));
    if (lane == 0) sh[w] = m;
    __syncthreads();
    if (tid == 0) {
        float a = sh[0];
        #pragma unroll
        for (int i = 1; i < 8; i++) a = fmaxf(a, sh[i]);
        res = a;
    }
    __syncthreads();
    float mm = res;
    float sum = 0.f;
    #pragma unroll
    for (int i = 0; i < 8; i++) { v[i] = __expf(v[i] - mm); sum += v[i]; }
    __syncthreads();
    #pragma unroll
    for (int o = 16; o; o >>= 1) sum += __shfl_xor_sync(0xffffffffu, sum, o);
    if (lane == 0) sh[w] = sum;
    __syncthreads();
    if (tid == 0) {
        float a = 0.f;
        #pragma unroll
        for (int i = 0; i < 8; i++) a += sh[i];
        res = a;
    }
    __syncthreads();
    float inv = 1.f / res;
    #pragma unroll
    for (int i = 0; i < 8; i++)
        ph[row * (long)T_ + tid + i*256] = __float2half_rn(v[i] * inv);
}

// ---------------- transpose fp32 -> split fp16 hi/lo ----------------
__global__ __launch_bounds__(256) void tr_split32_kernel(
    const float* __restrict__ in, __half* __restrict__ oh, __half* __restrict__ ol,
    int R, int Cc)
{
    long zo = (long)blockIdx.z * R * Cc;
    in += zo; oh += zo; ol += zo;
    __shared__ float t[32][33];
    int c0 = blockIdx.x * 32, r0 = blockIdx.y * 32;
    int tid = threadIdx.x;
    int tx = tid & 31, ty = tid >> 5;
    #pragma unroll
    for (int j = 0; j < 4; j++)
        t[ty + j*8][tx] = in[(long)(r0 + ty + j*8) * Cc + c0 + tx];
    __syncthreads();
    #pragma unroll
    for (int j = 0; j < 4; j++) {
        float v = t[tx][ty + j*8];
        __half hi, lo; fsplit(v, hi, lo);
        long idx = (long)(c0 + ty + j*8) * R + r0 + tx;
        oh[idx] = hi; ol[idx] = lo;
    }
}

// ---------------- transpose fp16 (hi only) ----------------
__global__ __launch_bounds__(256) void tr_h16_kernel(
    const __half* __restrict__ ih, __half* __restrict__ oh, int R, int Cc)
{
    long zo = (long)blockIdx.z * R * Cc;
    ih += zo; oh += zo;
    __shared__ __half th[32][34];
    int c0 = blockIdx.x * 32, r0 = blockIdx.y * 32;
    int tid = threadIdx.x;
    int tx = tid & 31, ty = tid >> 5;
    #pragma unroll
    for (int j = 0; j < 4; j++)
        th[ty + j*8][tx] = ih[(long)(r0 + ty + j*8) * Cc + c0 + tx];
    __syncthreads();
    #pragma unroll
    for (int j = 0; j < 4; j++)
        oh[(long)(c0 + ty + j*8) * R + r0 + tx] = th[tx][ty + j*8];
}

// ---------------- compensated FP16 tensor-core batched GEMM ----------------
// C[m,n] = alpha * sum_k A[m,k] * B[n,k]  (K-major fp16)
// Terms: hi*hi always; lo_A*hi_B iff ALO; hi_A*lo_B iff BLO.
// 128x128 CTA tile, BK=16, 8 warps of 64x32, 4-stage cp.async pipeline.
// OUT: 0 = fp32 (+bias/relu/res), 1 = fp16 hi/lo pair, 2 = QKV scatter, 3 = fp16 hi.
#define SLD 24
#define TILEH (128*SLD)
#define NSTG 4

template<bool ALO, bool BLO, bool RELU, bool BIAS, bool RES, int OUT>
__global__ __launch_bounds__(256, 2) void hgemm_kernel(
    int K,
    const __half* __restrict__ Ahp, const __half* __restrict__ Alp, int lda, long sAb, long sAh,
    const __half* __restrict__ Bhp, const __half* __restrict__ Blp, int ldb, long sBb, long sBh,
    float* __restrict__ Cf, __half* __restrict__ Ch, __half* __restrict__ Cl,
    int ldc, long sCb, long sCh,
    const float* __restrict__ bias,
    const float* __restrict__ res, int ldr, long sRb, long sRh,
    float alpha, int Hn,
    __half* __restrict__ kvH1, __half* __restrict__ kvL1,
    __half* __restrict__ kvH2, __half* __restrict__ kvL2)
{
    constexpr int NARR = 2 + (ALO ? 1 : 0) + (BLO ? 1 : 0);
    extern __shared__ __half dsm[];

    int z = blockIdx.z;
    int zb = z / Hn, zh = z - zb * Hn;
    Ahp += zb * sAb + zh * sAh;
    if (ALO) Alp += zb * sAb + zh * sAh;
    Bhp += zb * sBb + zh * sBh;
    if (BLO) Blp += zb * sBb + zh * sBh;
    long co = zb * sCb + zh * sCh;
    if (OUT == 0) Cf += co; else if (OUT == 1 || OUT == 3) { Ch += co; if (OUT == 1) Cl += co; }
    if (RES) res += zb * sRb + zh * sRh;

    const int m0 = blockIdx.y * 128;
    const int n0 = blockIdx.x * 128;
    const int tid  = threadIdx.x;
    const int lane = tid & 31;
    const int warp = tid >> 5;
    const int mwarp = (warp >> 2) * 64;
    const int nwarp = (warp & 3) * 32;
    const int g = lane >> 2;
    const int t = lane & 3;

    float acc[16][4];
    #pragma unroll
    for (int i = 0; i < 16; i++)
        #pragma unroll
        for (int j = 0; j < 4; j++) acc[i][j] = 0.f;

    const int ldrow = tid >> 1;
    const int ldseg = (tid & 1) * 8;
    const int nIter = K / 16;

    constexpr int BH_IDX = 1 + (ALO ? 1 : 0);          // index of B_hi array
    constexpr int BL_IDX = BH_IDX + 1;                 // index of B_lo array (if BLO)

    auto issue = [&](int it) {
        __half* base = dsm + (it & (NSTG-1)) * NARR * TILEH;
        int so = ldrow * SLD + ldseg;
        int k0 = it * 16;
        cp16h(base + so, Ahp + (long)(m0 + ldrow) * lda + k0 + ldseg);
        if (ALO) cp16h(base + TILEH + so, Alp + (long)(m0 + ldrow) * lda + k0 + ldseg);
        cp16h(base + BH_IDX*TILEH + so, Bhp + (long)(n0 + ldrow) * ldb + k0 + ldseg);
        if (BLO) cp16h(base + BL_IDX*TILEH + so, Blp + (long)(n0 + ldrow) * ldb + k0 + ldseg);
        asm volatile("cp.async.commit_group;\n");
    };

    const u32 smemU = (u32)__cvta_generic_to_shared(dsm);
    const u32 laneOff = (u32)((lane & 15) * (SLD * 2) + ((lane >> 4) & 1) * 16);

    issue(0); issue(1); issue(2);    // nIter >= 8 for all call sites

    for (int i = 0; i < nIter; i++) {
        asm volatile("cp.async.wait_group 2;\n");
        __syncthreads();
        if (i + 3 < nIter) issue(i + 3);
        else asm volatile("cp.async.commit_group;\n");   // keep group count invariant

        const u32 sb = smemU + (u32)((i & (NSTG-1)) * NARR * TILEH * 2);
        const u32 aH = sb;
        const u32 aL = sb + TILEH * 2;
        const u32 bH = sb + BH_IDX * TILEH * 2;
        const u32 bL = sb + BL_IDX * TILEH * 2;

        u32 ah[4][4], al[4][4], bh[4][2], bl[4][2];
        #pragma unroll
        for (int p = 0; p < 2; p++) {
            u32 r0, r1, r2, r3;
            u32 off = (u32)((nwarp + p * 16) * (SLD * 2)) + laneOff;
            ldsm4(bH + off, r0, r1, r2, r3);
            bh[2*p][0] = r0; bh[2*p+1][0] = r1; bh[2*p][1] = r2; bh[2*p+1][1] = r3;
            if (BLO) {
                ldsm4(bL + off, r0, r1, r2, r3);
                bl[2*p][0] = r0; bl[2*p+1][0] = r1; bl[2*p][1] = r2; bl[2*p+1][1] = r3;
            }
        }
        #pragma unroll
        for (int mt = 0; mt < 4; mt++) {
            u32 off = (u32)((mwarp + mt * 16) * (SLD * 2)) + laneOff;
            ldsm4(aH + off, ah[mt][0], ah[mt][1], ah[mt][2], ah[mt][3]);
            if (ALO) ldsm4(aL + off, al[mt][0], al[mt][1], al[mt][2], al[mt][3]);
        }

        #pragma unroll
        for (int mt = 0; mt < 4; mt++)
            #pragma unroll
            for (int nt = 0; nt < 4; nt++)
                mma16(acc[mt * 4 + nt], ah[mt], bh[nt]);   // hi*hi
        if (ALO) {
            #pragma unroll
            for (int mt = 0; mt < 4; mt++)
                #pragma unroll
                for (int nt = 0; nt < 4; nt++)
                    mma16(acc[mt * 4 + nt], al[mt], bh[nt]);   // lo*hi
        }
        if (BLO) {
            #pragma unroll
            for (int mt = 0; mt < 4; mt++)
                #pragma unroll
                for (int nt = 0; nt < 4; nt++)
                    mma16(acc[mt * 4 + nt], ah[mt], bl[nt]);   // hi*lo
        }
    }

    // ---- epilogue ----
    int qh = 0;
    __half *dH = Ch, *dL = Cl;
    if (OUT == 2) {
        int qsel = n0 >> 10;
        qh   = (n0 >> 7) & 7;
        dH = (qsel == 0) ? Ch : (qsel == 1) ? kvH1 : kvH2;
        dL = (qsel == 0) ? Cl : (qsel == 1) ? kvL1 : kvL2;
    }
    #pragma unroll
    for (int mt = 0; mt < 4; mt++) {
        #pragma unroll
        for (int nt = 0; nt < 4; nt++) {
            const float* a4 = acc[mt * 4 + nt];
            int rr = m0 + mwarp + mt * 16 + g;
            int cc = n0 + nwarp + nt * 8 + 2 * t;
            #pragma unroll
            for (int half = 0; half < 2; half++) {
                int m = rr + half * 8;
                float v0 = a4[half * 2 + 0] * alpha;
                float v1 = a4[half * 2 + 1] * alpha;
                if (BIAS) { v0 += bias[cc]; v1 += bias[cc + 1]; }
                if (RELU) { v0 = fmaxf(v0, 0.f); v1 = fmaxf(v1, 0.f); }
                if (RES) {
                    v0 += res[(long)m * ldr + cc];
                    v1 += res[(long)m * ldr + cc + 1];
                }
                if (OUT == 0) {
                    Cf[(long)m * ldc + cc]     = v0;
                    Cf[(long)m * ldc + cc + 1] = v1;
                } else if (OUT == 1) {
                    __half h0, l0, h1, l1;
                    fsplit(v0, h0, l0); fsplit(v1, h1, l1);
                    *reinterpret_cast<__half2*>(&Ch[(long)m * ldc + cc]) = __halves2half2(h0, h1);
                    *reinterpret_cast<__half2*>(&Cl[(long)m * ldc + cc]) = __halves2half2(l0, l1);
                } else if (OUT == 3) {
                    *reinterpret_cast<__half2*>(&Ch[(long)m * ldc + cc]) =
                        __halves2half2(__float2half_rn(v0), __float2half_rn(v1));
                } else {
                    long base = (((long)(m >> 11) * 8 + qh) * 2048 + (m & 2047)) * 128 + (cc & 127);
                    __half h0, l0, h1, l1;
                    fsplit(v0, h0, l0); fsplit(v1, h1, l1);
                    *reinterpret_cast<__half2*>(&dH[base]) = __halves2half2(h0, h1);
                    *reinterpret_cast<__half2*>(&dL[base]) = __halves2half2(l0, l1);
                }
            }
        }
    }
}

#define SMEM_4 (NSTG * 4 * TILEH * 2)   // 98304 (ALO && BLO)
#define SMEM_3 (NSTG * 3 * TILEH * 2)   // 73728 (one lo)
#define SMEM_2 (NSTG * 2 * TILEH * 2)   // 49152 (hi only)

// ---------------- launch ----------------
extern "C" void kernel_launch(void* const* d_in, const int* in_sizes, int n_in,
                              void* d_out, int out_size)
{
    const float* x     = (const float*)d_in[0];
    const float* wq    = (const float*)d_in[1];
    const float* wk    = (const float*)d_in[2];
    const float* wv    = (const float*)d_in[3];
    const float* w1    = (const float*)d_in[4];
    const float* b1    = (const float*)d_in[5];
    const float* w2    = (const float*)d_in[6];
    const float* b2    = (const float*)d_in[7];
    const float* ln1_g = (const float*)d_in[8];
    const float* ln1_b = (const float*)d_in[9];
    const float* ln2_g = (const float*)d_in[10];
    const float* ln2_b = (const float*)d_in[11];
    float* out = (float*)d_out;

    __half *hH,*hL, *wqkvTH,*wqkvTL, *w1TH,*w1TL, *w2TH,*w2TL;
    __half *qH,*qL, *kH,*kL, *vH,*vL, *vtH, *pH, *f1H;
    float *sc, *xmid;
    cudaGetSymbolAddress((void**)&hH, g_hH);   cudaGetSymbolAddress((void**)&hL, g_hL);
    cudaGetSymbolAddress((void**)&wqkvTH, g_wqkvTH); cudaGetSymbolAddress((void**)&wqkvTL, g_wqkvTL);
    cudaGetSymbolAddress((void**)&w1TH, g_w1TH); cudaGetSymbolAddress((void**)&w1TL, g_w1TL);
    cudaGetSymbolAddress((void**)&w2TH, g_w2TH); cudaGetSymbolAddress((void**)&w2TL, g_w2TL);
    cudaGetSymbolAddress((void**)&qH, g_qH);   cudaGetSymbolAddress((void**)&qL, g_qL);
    cudaGetSymbolAddress((void**)&kH, g_kH);   cudaGetSymbolAddress((void**)&kL, g_kL);
    cudaGetSymbolAddress((void**)&vH, g_vH);   cudaGetSymbolAddress((void**)&vL, g_vL);
    cudaGetSymbolAddress((void**)&vtH, g_vtH);
    cudaGetSymbolAddress((void**)&pH, g_pH);
    cudaGetSymbolAddress((void**)&f1H, g_ff1H);
    cudaGetSymbolAddress((void**)&sc, g_scores);
    cudaGetSymbolAddress((void**)&xmid, g_xmid);

    cudaFuncSetAttribute(hgemm_kernel<true,true,false,false,false,2>,
                         cudaFuncAttributeMaxDynamicSharedMemorySize, SMEM_4);
    cudaFuncSetAttribute(hgemm_kernel<true,true,false,false,false,0>,
                         cudaFuncAttributeMaxDynamicSharedMemorySize, SMEM_4);
    cudaFuncSetAttribute(hgemm_kernel<false,false,false,false,true,0>,
                         cudaFuncAttributeMaxDynamicSharedMemorySize, SMEM_2);
    cudaFuncSetAttribute(hgemm_kernel<true,false,true,true,false,3>,
                         cudaFuncAttributeMaxDynamicSharedMemorySize, SMEM_3);
    cudaFuncSetAttribute(hgemm_kernel<false,true,false,true,true,0>,
                         cudaFuncAttributeMaxDynamicSharedMemorySize, SMEM_3);

    const float scale = 11.3137084989847604f;  // sqrt(128)
    const long HTD  = (long)T_ * DH_;
    const long BTD  = (long)H_ * HTD;
    const long STT  = (long)T_ * T_;
    const long SBB  = (long)H_ * STT;
    const long TC   = (long)T_ * C_;

    // ---- weight pre-pass: wq/wk/wv -> concatenated [3072][1024]; w1T, w2T ----
    tr_split32_kernel<<<dim3(DH_/32, C_/32, H_), 256>>>(wq, wqkvTH,           wqkvTL,           C_, DH_);
    tr_split32_kernel<<<dim3(DH_/32, C_/32, H_), 256>>>(wk, wqkvTH + C_*C_,   wqkvTL + C_*C_,   C_, DH_);
    tr_split32_kernel<<<dim3(DH_/32, C_/32, H_), 256>>>(wv, wqkvTH + 2*C_*C_, wqkvTL + 2*C_*C_, C_, DH_);
    tr_split32_kernel<<<dim3(DFF_/32, C_/32, 1), 256>>>(w1, w1TH, w1TL, C_, DFF_);
    tr_split32_kernel<<<dim3(C_/32, DFF_/32, 1), 256>>>(w2, w2TH, w2TL, DFF_, C_);

    // ---- LN1 ----
    ln_split_kernel<<<ROWS_, 256>>>(x, ln1_g, ln1_b, hH, hL);

    // ---- fused QKV (3-term): [8192x1024] @ [3072x1024]^T, scatter to q/k/v ----
    hgemm_kernel<true,true,false,false,false,2><<<dim3(3*C_/128, ROWS_/128, 1), 256, SMEM_4>>>(
        C_, hH, hL, C_, 0, 0,  wqkvTH, wqkvTL, C_, 0, 0,
        nullptr, qH, qL, 0, 0, 0,  nullptr, nullptr, 0, 0, 0, 1.f, 1,
        kH, kL, vH, vL);

    // ---- V^T per (b,h): [T][Dh] -> [Dh][T] (hi only; PV is 1-term) ----
    tr_h16_kernel<<<dim3(DH_/32, T_/32, B_*H_), 256>>>(vH, vtH, T_, DH_);

    // ---- scores = Q @ K^T * sqrt(Dh) (3-term) ----
    hgemm_kernel<true,true,false,false,false,0><<<dim3(T_/128, T_/128, B_*H_), 256, SMEM_4>>>(
        DH_, qH, qL, DH_, BTD, HTD,  kH, kL, DH_, BTD, HTD,
        sc, nullptr, nullptr, T_, SBB, STT,  nullptr, nullptr, 0, 0, 0, scale, H_,
        nullptr, nullptr, nullptr, nullptr);

    // ---- softmax -> probs fp16 ----
    softmax_h_kernel<<<B_*H_*T_, 256>>>(sc, pH);

    // ---- O = P @ V (+x residual) -> xmid;  1-term (P hi, V hi) ----
    hgemm_kernel<false,false,false,false,true,0><<<dim3(1, T_/128, B_*H_), 256, SMEM_2>>>(
        T_, pH, nullptr, T_, SBB, STT,  vtH, nullptr, T_, BTD, HTD,
        xmid, nullptr, nullptr, C_, TC, DH_,  nullptr, x, C_, TC, DH_, 1.f, H_,
        nullptr, nullptr, nullptr, nullptr);

    // ---- LN2 ----
    ln_split_kernel<<<ROWS_, 256>>>(xmid, ln2_g, ln2_b, hH, hL);

    // ---- FF1 (2-term: h hi/lo, w1 hi): relu(h @ w1 + b1) -> fp16 hi ----
    hgemm_kernel<true,false,true,true,false,3><<<dim3(DFF_/128, ROWS_/128, 1), 256, SMEM_3>>>(
        C_, hH, hL, C_, 0, 0,  w1TH, nullptr, C_, 0, 0,
        nullptr, f1H, nullptr, DFF_, 0, 0,  b1, nullptr, 0, 0, 0, 1.f, 1,
        nullptr, nullptr, nullptr, nullptr);

    // ---- FF2 (2-term: ff1 hi, w2 hi/lo): out = xmid + ff1 @ w2 + b2 ----
    hgemm_kernel<false,true,false,true,true,0><<<dim3(C_/128, ROWS_/128, 1), 256, SMEM_3>>>(
        DFF_, f1H, nullptr, DFF_, 0, 0,  w2TH, w2TL, DFF_, 0, 0,
        out, nullptr, nullptr, C_, 0, 0,  b2, xmid, C_, 0, 0, 1.f, 1,
        nullptr, nullptr, nullptr, nullptr);
}

// round 16
// speedup vs baseline: 2.3373x; 1.1675x over previous
#include <cuda_runtime.h>
#include <cuda_fp16.h>
#include <math.h>

// ---------------- problem dims ----------------
#define B_  4
#define T_  2048
#define C_  1024
#define H_  8
#define DH_ 128
#define DFF_ 4096
#define ROWS_ (B_*T_)          // 8192

typedef unsigned int u32;

// ---------------- scratch (device globals; no allocs allowed) ----------------
__device__ __align__(16) __half g_hH[ROWS_*C_],  g_hL[ROWS_*C_];          // LN out
__device__ __align__(16) __half g_wqkvTH[3*C_*C_], g_wqkvTL[3*C_*C_];     // [3072][1024]
__device__ __align__(16) __half g_w1TH[C_*DFF_];                          // [Dff][C] hi
__device__ __align__(16) __half g_w2TH[C_*DFF_],   g_w2TL[C_*DFF_];       // [C][Dff]
__device__ __align__(16) __half g_qH[ROWS_*C_],  g_qL[ROWS_*C_];          // [B,H,T,Dh]
__device__ __align__(16) __half g_kH[ROWS_*C_],  g_kL[ROWS_*C_];
__device__ __align__(16) __half g_vH[ROWS_*C_],  g_vL[ROWS_*C_];
__device__ __align__(16) __half g_vtH[ROWS_*C_];                          // [B,H,Dh,T] hi
__device__ float g_scores[(long)B_*H_*T_*T_];
__device__ __align__(16) __half g_pH[(long)B_*H_*T_*T_];                  // probs (fp16 only)
__device__ __align__(16) __half g_ff1H[(long)ROWS_*DFF_];                 // ff1 (fp16 only)
__device__ float g_xmid[ROWS_*C_];

// ---------------- helpers ----------------
__device__ __forceinline__ void fsplit(float v, __half& hi, __half& lo) {
    hi = __float2half_rn(v);
    lo = __float2half_rn(v - __half2float(hi));
}
__device__ __forceinline__ void ldsm4(u32 addr, u32& r0, u32& r1, u32& r2, u32& r3) {
    asm volatile("ldmatrix.sync.aligned.m8n8.x4.shared.b16 {%0,%1,%2,%3}, [%4];"
                 : "=r"(r0), "=r"(r1), "=r"(r2), "=r"(r3) : "r"(addr));
}
__device__ __forceinline__ void mma16(float* c, const u32* a, const u32* b) {
    asm("mma.sync.aligned.m16n8k16.row.col.f32.f16.f16.f32 "
        "{%0,%1,%2,%3}, {%4,%5,%6,%7}, {%8,%9}, {%0,%1,%2,%3};\n"
        : "+f"(c[0]), "+f"(c[1]), "+f"(c[2]), "+f"(c[3])
        : "r"(a[0]), "r"(a[1]), "r"(a[2]), "r"(a[3]), "r"(b[0]), "r"(b[1]));
}
__device__ __forceinline__ void cp16h(__half* smem_dst, const __half* gmem_src) {
    u32 s = (u32)__cvta_generic_to_shared(smem_dst);
    asm volatile("cp.async.cg.shared.global [%0], [%1], 16;\n" :: "r"(s), "l"(gmem_src));
}

// ---------------- LayerNorm -> fp16 hi/lo ----------------
__global__ __launch_bounds__(256) void ln_split_kernel(
    const float* __restrict__ x, const float* __restrict__ g,
    const float* __restrict__ b, __half* __restrict__ oh, __half* __restrict__ ol)
{
    long row = blockIdx.x;
    const float* p = x + row * C_;
    int tid = threadIdx.x;
    float v[4];
    float s = 0.f, s2 = 0.f;
    #pragma unroll
    for (int i = 0; i < 4; i++) {
        v[i] = p[tid + i*256];
        s += v[i]; s2 += v[i]*v[i];
    }
    __shared__ float sh[2][8];
    #pragma unroll
    for (int o = 16; o; o >>= 1) {
        s  += __shfl_xor_sync(0xffffffffu, s,  o);
        s2 += __shfl_xor_sync(0xffffffffu, s2, o);
    }
    int lane = tid & 31, w = tid >> 5;
    if (lane == 0) { sh[0][w] = s; sh[1][w] = s2; }
    __syncthreads();
    if (tid == 0) {
        float a = 0.f, c = 0.f;
        #pragma unroll
        for (int i = 0; i < 8; i++) { a += sh[0][i]; c += sh[1][i]; }
        sh[0][0] = a; sh[1][0] = c;
    }
    __syncthreads();
    float mu  = sh[0][0] * (1.f / C_);
    float var = sh[1][0] * (1.f / C_) - mu * mu;
    float rstd = rsqrtf(var + 1e-5f);
    #pragma unroll
    for (int i = 0; i < 4; i++) {
        int n = tid + i*256;
        float o = (v[i] - mu) * rstd * g[n] + b[n];
        __half hi, lo; fsplit(o, hi, lo);
        oh[row * C_ + n] = hi;
        ol[row * C_ + n] = lo;
    }
}

// ---------------- Softmax -> fp16 probs (hi only) ----------------
__global__ __launch_bounds__(256) void softmax_h_kernel(
    const float* __restrict__ sc, __half* __restrict__ ph)
{
    long row = blockIdx.x;
    const float* p = sc + row * (long)T_;
    int tid = threadIdx.x;
    float v[8];
    float m = -1e30f;
    #pragma unroll
    for (int i = 0; i < 8; i++) { v[i] = p[tid + i*256]; m = fmaxf(m, v[i]); }
    __shared__ float sh[8];
    __shared__ float res;
    int lane = tid & 31, w = tid >> 5;
    #pragma unroll
    for (int o = 16; o; o >>= 1) m = fmaxf(m, __shfl_xor_sync(0xffffffffu, m, o));
    if (lane == 0) sh[w] = m;
    __syncthreads();
    if (tid == 0) {
        float a = sh[0];
        #pragma unroll
        for (int i = 1; i < 8; i++) a = fmaxf(a, sh[i]);
        res = a;
    }
    __syncthreads();
    float mm = res;
    float sum = 0.f;
    #pragma unroll
    for (int i = 0; i < 8; i++) { v[i] = __expf(v[i] - mm); sum += v[i]; }
    __syncthreads();
    #pragma unroll
    for (int o = 16; o; o >>= 1) sum += __shfl_xor_sync(0xffffffffu, sum, o);
    if (lane == 0) sh[w] = sum;
    __syncthreads();
    if (tid == 0) {
        float a = 0.f;
        #pragma unroll
        for (int i = 0; i < 8; i++) a += sh[i];
        res = a;
    }
    __syncthreads();
    float inv = 1.f / res;
    #pragma unroll
    for (int i = 0; i < 8; i++)
        ph[row * (long)T_ + tid + i*256] = __float2half_rn(v[i] * inv);
}

// ---------------- transpose fp32 -> split fp16 hi/lo ----------------
__global__ __launch_bounds__(256) void tr_split32_kernel(
    const float* __restrict__ in, __half* __restrict__ oh, __half* __restrict__ ol,
    int R, int Cc)
{
    long zo = (long)blockIdx.z * R * Cc;
    in += zo; oh += zo; if (ol) ol += zo;
    __shared__ float t[32][33];
    int c0 = blockIdx.x * 32, r0 = blockIdx.y * 32;
    int tid = threadIdx.x;
    int tx = tid & 31, ty = tid >> 5;
    #pragma unroll
    for (int j = 0; j < 4; j++)
        t[ty + j*8][tx] = in[(long)(r0 + ty + j*8) * Cc + c0 + tx];
    __syncthreads();
    #pragma unroll
    for (int j = 0; j < 4; j++) {
        float v = t[tx][ty + j*8];
        __half hi, lo; fsplit(v, hi, lo);
        long idx = (long)(c0 + ty + j*8) * R + r0 + tx;
        oh[idx] = hi;
        if (ol) ol[idx] = lo;
    }
}

// ---------------- transpose fp16 (hi only) ----------------
__global__ __launch_bounds__(256) void tr_h16_kernel(
    const __half* __restrict__ ih, __half* __restrict__ oh, int R, int Cc)
{
    long zo = (long)blockIdx.z * R * Cc;
    ih += zo; oh += zo;
    __shared__ __half th[32][34];
    int c0 = blockIdx.x * 32, r0 = blockIdx.y * 32;
    int tid = threadIdx.x;
    int tx = tid & 31, ty = tid >> 5;
    #pragma unroll
    for (int j = 0; j < 4; j++)
        th[ty + j*8][tx] = ih[(long)(r0 + ty + j*8) * Cc + c0 + tx];
    __syncthreads();
    #pragma unroll
    for (int j = 0; j < 4; j++)
        oh[(long)(c0 + ty + j*8) * R + r0 + tx] = th[tx][ty + j*8];
}

// ---------------- compensated FP16 tensor-core batched GEMM ----------------
// C[m,n] = alpha * sum_k A[m,k] * B[n,k]  (K-major fp16)
// Terms: hi*hi always; lo_A*hi_B iff ALO; hi_A*lo_B iff BLO.
// 128x128 CTA tile, BK=16, 8 warps of 64x32, 4-stage cp.async pipeline.
// OUT: 0 = fp32 (+bias/relu/res), 2 = QKV scatter (nqoff selects q/k/v), 3 = fp16 hi.
#define SLD 24
#define TILEH (128*SLD)
#define NSTG 4

template<bool ALO, bool BLO, bool RELU, bool BIAS, bool RES, int OUT>
__global__ __launch_bounds__(256, 2) void hgemm_kernel(
    int K,
    const __half* __restrict__ Ahp, const __half* __restrict__ Alp, int lda, long sAb, long sAh,
    const __half* __restrict__ Bhp, const __half* __restrict__ Blp, int ldb, long sBb, long sBh,
    float* __restrict__ Cf, __half* __restrict__ Ch, __half* __restrict__ Cl,
    int ldc, long sCb, long sCh,
    const float* __restrict__ bias,
    const float* __restrict__ res, int ldr, long sRb, long sRh,
    float alpha, int Hn, int nqoff,
    __half* __restrict__ kvH1, __half* __restrict__ kvL1,
    __half* __restrict__ kvH2, __half* __restrict__ kvL2)
{
    constexpr int NARR = 2 + (ALO ? 1 : 0) + (BLO ? 1 : 0);
    extern __shared__ __half dsm[];

    int z = blockIdx.z;
    int zb = z / Hn, zh = z - zb * Hn;
    Ahp += zb * sAb + zh * sAh;
    if (ALO) Alp += zb * sAb + zh * sAh;
    Bhp += zb * sBb + zh * sBh;
    if (BLO) Blp += zb * sBb + zh * sBh;
    long co = zb * sCb + zh * sCh;
    if (OUT == 0) Cf += co; else if (OUT == 3) Ch += co;
    if (RES) res += zb * sRb + zh * sRh;

    const int m0 = blockIdx.y * 128;
    const int n0 = blockIdx.x * 128;
    const int tid  = threadIdx.x;
    const int lane = tid & 31;
    const int warp = tid >> 5;
    const int mwarp = (warp >> 2) * 64;
    const int nwarp = (warp & 3) * 32;
    const int g = lane >> 2;
    const int t = lane & 3;

    float acc[16][4];
    #pragma unroll
    for (int i = 0; i < 16; i++)
        #pragma unroll
        for (int j = 0; j < 4; j++) acc[i][j] = 0.f;

    const int ldrow = tid >> 1;
    const int ldseg = (tid & 1) * 8;
    const int nIter = K / 16;

    constexpr int BH_IDX = 1 + (ALO ? 1 : 0);          // index of B_hi array
    constexpr int BL_IDX = BH_IDX + 1;                 // index of B_lo array (if BLO)

    auto issue = [&](int it) {
        __half* base = dsm + (it & (NSTG-1)) * NARR * TILEH;
        int so = ldrow * SLD + ldseg;
        int k0 = it * 16;
        cp16h(base + so, Ahp + (long)(m0 + ldrow) * lda + k0 + ldseg);
        if (ALO) cp16h(base + TILEH + so, Alp + (long)(m0 + ldrow) * lda + k0 + ldseg);
        cp16h(base + BH_IDX*TILEH + so, Bhp + (long)(n0 + ldrow) * ldb + k0 + ldseg);
        if (BLO) cp16h(base + BL_IDX*TILEH + so, Blp + (long)(n0 + ldrow) * ldb + k0 + ldseg);
        asm volatile("cp.async.commit_group;\n");
    };

    const u32 smemU = (u32)__cvta_generic_to_shared(dsm);
    const u32 laneOff = (u32)((lane & 15) * (SLD * 2) + ((lane >> 4) & 1) * 16);

    issue(0); issue(1); issue(2);    // nIter >= 8 for all call sites

    for (int i = 0; i < nIter; i++) {
        asm volatile("cp.async.wait_group 2;\n");
        __syncthreads();
        if (i + 3 < nIter) issue(i + 3);
        else asm volatile("cp.async.commit_group;\n");   // keep group count invariant

        const u32 sb = smemU + (u32)((i & (NSTG-1)) * NARR * TILEH * 2);
        const u32 aH = sb;
        const u32 aL = sb + TILEH * 2;
        const u32 bH = sb + BH_IDX * TILEH * 2;
        const u32 bL = sb + BL_IDX * TILEH * 2;

        u32 ah[4][4], al[4][4], bh[4][2], bl[4][2];
        #pragma unroll
        for (int p = 0; p < 2; p++) {
            u32 r0, r1, r2, r3;
            u32 off = (u32)((nwarp + p * 16) * (SLD * 2)) + laneOff;
            ldsm4(bH + off, r0, r1, r2, r3);
            bh[2*p][0] = r0; bh[2*p+1][0] = r1; bh[2*p][1] = r2; bh[2*p+1][1] = r3;
            if (BLO) {
                ldsm4(bL + off, r0, r1, r2, r3);
                bl[2*p][0] = r0; bl[2*p+1][0] = r1; bl[2*p][1] = r2; bl[2*p+1][1] = r3;
            }
        }
        #pragma unroll
        for (int mt = 0; mt < 4; mt++) {
            u32 off = (u32)((mwarp + mt * 16) * (SLD * 2)) + laneOff;
            ldsm4(aH + off, ah[mt][0], ah[mt][1], ah[mt][2], ah[mt][3]);
            if (ALO) ldsm4(aL + off, al[mt][0], al[mt][1], al[mt][2], al[mt][3]);
        }

        #pragma unroll
        for (int mt = 0; mt < 4; mt++)
            #pragma unroll
            for (int nt = 0; nt < 4; nt++)
                mma16(acc[mt * 4 + nt], ah[mt], bh[nt]);   // hi*hi
        if (ALO) {
            #pragma unroll
            for (int mt = 0; mt < 4; mt++)
                #pragma unroll
                for (int nt = 0; nt < 4; nt++)
                    mma16(acc[mt * 4 + nt], al[mt], bh[nt]);   // lo*hi
        }
        if (BLO) {
            #pragma unroll
            for (int mt = 0; mt < 4; mt++)
                #pragma unroll
                for (int nt = 0; nt < 4; nt++)
                    mma16(acc[mt * 4 + nt], ah[mt], bl[nt]);   // hi*lo
        }
    }

    // ---- epilogue ----
    int qh = 0;
    __half *dH = Ch, *dL = Cl;
    if (OUT == 2) {
        int gn0  = n0 + nqoff;
        int qsel = gn0 >> 10;
        qh   = (gn0 >> 7) & 7;
        dH = (qsel == 0) ? Ch : (qsel == 1) ? kvH1 : kvH2;
        dL = (qsel == 0) ? Cl : (qsel == 1) ? kvL1 : kvL2;
    }
    #pragma unroll
    for (int mt = 0; mt < 4; mt++) {
        #pragma unroll
        for (int nt = 0; nt < 4; nt++) {
            const float* a4 = acc[mt * 4 + nt];
            int rr = m0 + mwarp + mt * 16 + g;
            int cc = n0 + nwarp + nt * 8 + 2 * t;
            #pragma unroll
            for (int half = 0; half < 2; half++) {
                int m = rr + half * 8;
                float v0 = a4[half * 2 + 0] * alpha;
                float v1 = a4[half * 2 + 1] * alpha;
                if (BIAS) { v0 += bias[cc]; v1 += bias[cc + 1]; }
                if (RELU) { v0 = fmaxf(v0, 0.f); v1 = fmaxf(v1, 0.f); }
                if (RES) {
                    v0 += res[(long)m * ldr + cc];
                    v1 += res[(long)m * ldr + cc + 1];
                }
                if (OUT == 0) {
                    Cf[(long)m * ldc + cc]     = v0;
                    Cf[(long)m * ldc + cc + 1] = v1;
                } else if (OUT == 3) {
                    *reinterpret_cast<__half2*>(&Ch[(long)m * ldc + cc]) =
                        __halves2half2(__float2half_rn(v0), __float2half_rn(v1));
                } else {
                    long base = (((long)(m >> 11) * 8 + qh) * 2048 + (m & 2047)) * 128 + (cc & 127);
                    __half h0, l0, h1, l1;
                    fsplit(v0, h0, l0); fsplit(v1, h1, l1);
                    *reinterpret_cast<__half2*>(&dH[base]) = __halves2half2(h0, h1);
                    *reinterpret_cast<__half2*>(&dL[base]) = __halves2half2(l0, l1);
                }
            }
        }
    }
}

#define SMEM_4 (NSTG * 4 * TILEH * 2)   // 98304 (ALO && BLO)
#define SMEM_3 (NSTG * 3 * TILEH * 2)   // 73728 (one lo)
#define SMEM_2 (NSTG * 2 * TILEH * 2)   // 49152 (hi only)

// ---------------- launch ----------------
extern "C" void kernel_launch(void* const* d_in, const int* in_sizes, int n_in,
                              void* d_out, int out_size)
{
    const float* x     = (const float*)d_in[0];
    const float* wq    = (const float*)d_in[1];
    const float* wk    = (const float*)d_in[2];
    const float* wv    = (const float*)d_in[3];
    const float* w1    = (const float*)d_in[4];
    const float* b1    = (const float*)d_in[5];
    const float* w2    = (const float*)d_in[6];
    const float* b2    = (const float*)d_in[7];
    const float* ln1_g = (const float*)d_in[8];
    const float* ln1_b = (const float*)d_in[9];
    const float* ln2_g = (const float*)d_in[10];
    const float* ln2_b = (const float*)d_in[11];
    float* out = (float*)d_out;

    __half *hH,*hL, *wqkvTH,*wqkvTL, *w1TH, *w2TH,*w2TL;
    __half *qH,*qL, *kH,*kL, *vH,*vL, *vtH, *pH, *f1H;
    float *sc, *xmid;
    cudaGetSymbolAddress((void**)&hH, g_hH);   cudaGetSymbolAddress((void**)&hL, g_hL);
    cudaGetSymbolAddress((void**)&wqkvTH, g_wqkvTH); cudaGetSymbolAddress((void**)&wqkvTL, g_wqkvTL);
    cudaGetSymbolAddress((void**)&w1TH, g_w1TH);
    cudaGetSymbolAddress((void**)&w2TH, g_w2TH); cudaGetSymbolAddress((void**)&w2TL, g_w2TL);
    cudaGetSymbolAddress((void**)&qH, g_qH);   cudaGetSymbolAddress((void**)&qL, g_qL);
    cudaGetSymbolAddress((void**)&kH, g_kH);   cudaGetSymbolAddress((void**)&kL, g_kL);
    cudaGetSymbolAddress((void**)&vH, g_vH);   cudaGetSymbolAddress((void**)&vL, g_vL);
    cudaGetSymbolAddress((void**)&vtH, g_vtH);
    cudaGetSymbolAddress((void**)&pH, g_pH);
    cudaGetSymbolAddress((void**)&f1H, g_ff1H);
    cudaGetSymbolAddress((void**)&sc, g_scores);
    cudaGetSymbolAddress((void**)&xmid, g_xmid);

    cudaFuncSetAttribute(hgemm_kernel<true,true,false,false,false,2>,
                         cudaFuncAttributeMaxDynamicSharedMemorySize, SMEM_4);
    cudaFuncSetAttribute(hgemm_kernel<false,false,false,false,false,2>,
                         cudaFuncAttributeMaxDynamicSharedMemorySize, SMEM_2);
    cudaFuncSetAttribute(hgemm_kernel<true,true,false,false,false,0>,
                         cudaFuncAttributeMaxDynamicSharedMemorySize, SMEM_4);
    cudaFuncSetAttribute(hgemm_kernel<false,false,false,false,true,0>,
                         cudaFuncAttributeMaxDynamicSharedMemorySize, SMEM_2);
    cudaFuncSetAttribute(hgemm_kernel<false,false,true,true,false,3>,
                         cudaFuncAttributeMaxDynamicSharedMemorySize, SMEM_2);
    cudaFuncSetAttribute(hgemm_kernel<false,true,false,true,true,0>,
                         cudaFuncAttributeMaxDynamicSharedMemorySize, SMEM_3);

    const float scale = 11.3137084989847604f;  // sqrt(128)
    const long HTD  = (long)T_ * DH_;
    const long BTD  = (long)H_ * HTD;
    const long STT  = (long)T_ * T_;
    const long SBB  = (long)H_ * STT;
    const long TC   = (long)T_ * C_;

    // ---- weight pre-pass: wq/wk/wv -> concatenated [3072][1024]; w1T (hi), w2T ----
    tr_split32_kernel<<<dim3(DH_/32, C_/32, H_), 256>>>(wq, wqkvTH,           wqkvTL,           C_, DH_);
    tr_split32_kernel<<<dim3(DH_/32, C_/32, H_), 256>>>(wk, wqkvTH + C_*C_,   wqkvTL + C_*C_,   C_, DH_);
    tr_split32_kernel<<<dim3(DH_/32, C_/32, H_), 256>>>(wv, wqkvTH + 2*C_*C_, nullptr,          C_, DH_);
    tr_split32_kernel<<<dim3(DFF_/32, C_/32, 1), 256>>>(w1, w1TH, nullptr, C_, DFF_);
    tr_split32_kernel<<<dim3(C_/32, DFF_/32, 1), 256>>>(w2, w2TH, w2TL, DFF_, C_);

    // ---- LN1 ----
    ln_split_kernel<<<ROWS_, 256>>>(x, ln1_g, ln1_b, hH, hL);

    // ---- QK (3-term): [8192x1024] @ [2048x1024]^T, scatter to q/k ----
    hgemm_kernel<true,true,false,false,false,2><<<dim3(2*C_/128, ROWS_/128, 1), 256, SMEM_4>>>(
        C_, hH, hL, C_, 0, 0,  wqkvTH, wqkvTL, C_, 0, 0,
        nullptr, qH, qL, 0, 0, 0,  nullptr, nullptr, 0, 0, 0, 1.f, 1, 0,
        kH, kL, vH, vL);

    // ---- V (1-term): [8192x1024] @ [1024x1024]^T, scatter to v ----
    hgemm_kernel<false,false,false,false,false,2><<<dim3(C_/128, ROWS_/128, 1), 256, SMEM_2>>>(
        C_, hH, nullptr, C_, 0, 0,  wqkvTH + 2*C_*C_, nullptr, C_, 0, 0,
        nullptr, qH, qL, 0, 0, 0,  nullptr, nullptr, 0, 0, 0, 1.f, 1, 2*C_,
        kH, kL, vH, vL);

    // ---- V^T per (b,h): [T][Dh] -> [Dh][T] (hi only; PV is 1-term) ----
    tr_h16_kernel<<<dim3(DH_/32, T_/32, B_*H_), 256>>>(vH, vtH, T_, DH_);

    // ---- scores = Q @ K^T * sqrt(Dh) (3-term) ----
    hgemm_kernel<true,true,false,false,false,0><<<dim3(T_/128, T_/128, B_*H_), 256, SMEM_4>>>(
        DH_, qH, qL, DH_, BTD, HTD,  kH, kL, DH_, BTD, HTD,
        sc, nullptr, nullptr, T_, SBB, STT,  nullptr, nullptr, 0, 0, 0, scale, H_, 0,
        nullptr, nullptr, nullptr, nullptr);

    // ---- softmax -> probs fp16 ----
    softmax_h_kernel<<<B_*H_*T_, 256>>>(sc, pH);

    // ---- O = P @ V (+x residual) -> xmid;  1-term (P hi, V hi) ----
    hgemm_kernel<false,false,false,false,true,0><<<dim3(1, T_/128, B_*H_), 256, SMEM_2>>>(
        T_, pH, nullptr, T_, SBB, STT,  vtH, nullptr, T_, BTD, HTD,
        xmid, nullptr, nullptr, C_, TC, DH_,  nullptr, x, C_, TC, DH_, 1.f, H_, 0,
        nullptr, nullptr, nullptr, nullptr);

    // ---- LN2 ----
    ln_split_kernel<<<ROWS_, 256>>>(xmid, ln2_g, ln2_b, hH, hL);

    // ---- FF1 (1-term: h hi, w1 hi): relu(h @ w1 + b1) -> fp16 hi ----
    hgemm_kernel<false,false,true,true,false,3><<<dim3(DFF_/128, ROWS_/128, 1), 256, SMEM_2>>>(
        C_, hH, nullptr, C_, 0, 0,  w1TH, nullptr, C_, 0, 0,
        nullptr, f1H, nullptr, DFF_, 0, 0,  b1, nullptr, 0, 0, 0, 1.f, 1, 0,
        nullptr, nullptr, nullptr, nullptr);

    // ---- FF2 (2-term: ff1 hi, w2 hi/lo): out = xmid + ff1 @ w2 + b2 ----
    hgemm_kernel<false,true,false,true,true,0><<<dim3(C_/128, ROWS_/128, 1), 256, SMEM_3>>>(
        DFF_, f1H, nullptr, DFF_, 0, 0,  w2TH, w2TL, DFF_, 0, 0,
        out, nullptr, nullptr, C_, 0, 0,  b2, xmid, C_, 0, 0, 1.f, 1, 0,
        nullptr, nullptr, nullptr, nullptr);
}